// round 1
// baseline (speedup 1.0000x reference)
#include <cuda_runtime.h>
#include <cuda_bf16.h>

// Problem constants
#define BATCH   16
#define IN_CH   256
#define NTOK    1024          // H*W = 32*32
#define NHEAD   8
#define DH      64            // qk head dim
#define DV      64            // v head dim
#define QKV_OUT 1536
#define SCALE   0.125f        // dh^-0.5

// Scratch: [B, H, N, D] layouts
__device__ __align__(16) float g_q[BATCH * NHEAD * NTOK * DH];
__device__ __align__(16) float g_k[BATCH * NHEAD * NTOK * DH];
__device__ __align__(16) float g_v[BATCH * NHEAD * NTOK * DV];
__device__ __align__(16) float g_o[BATCH * NHEAD * NTOK * DV];

// ---------------------------------------------------------------------------
// Kernel 1: QKV 1x1-conv GEMM.  qkv[b,o,n] = sum_c w[o,c]*x[b,c,n] + bias[o]
// Scatters into g_q/g_k/g_v with [b,h,n,d] layout; q pre-scaled by dh^-0.5.
// Tile 64(o) x 64(n) x 32(c), 256 threads, 4x4 micro-tile.
// acc[i][j]: i indexes n (ty), j indexes o (tx) so that d=o%64 is thread-fast
// -> coalesced float4 stores into [.., n, d].
// ---------------------------------------------------------------------------
__global__ void qkv_gemm_kernel(const float* __restrict__ x,
                                const float* __restrict__ w,
                                const float* __restrict__ bias)
{
    __shared__ float Ws[64][33];   // [o][c] padded
    __shared__ float Xs[32][64];   // [c][n]

    const int b  = blockIdx.z;
    const int oT = blockIdx.y * 64;
    const int nT = blockIdx.x * 64;
    const int t  = threadIdx.x;
    const int tx = t & 15;
    const int ty = t >> 4;

    const float* xb = x + (size_t)b * IN_CH * NTOK;

    float acc[4][4];
#pragma unroll
    for (int i = 0; i < 4; i++)
#pragma unroll
        for (int j = 0; j < 4; j++) acc[i][j] = 0.f;

    const int wk  = t & 31, wr0 = t >> 5;   // W loader
    const int xc  = t & 63, xk0 = t >> 6;   // X loader

    for (int kk = 0; kk < IN_CH; kk += 32) {
#pragma unroll
        for (int i = 0; i < 8; i++) {
            int r = wr0 + i * 8;
            Ws[r][wk] = w[(size_t)(oT + r) * IN_CH + kk + wk];
        }
#pragma unroll
        for (int i = 0; i < 8; i++) {
            int k = xk0 + i * 4;
            Xs[k][xc] = xb[(size_t)(kk + k) * NTOK + nT + xc];
        }
        __syncthreads();

#pragma unroll
        for (int k = 0; k < 32; k++) {
            float xa[4], wb_[4];
#pragma unroll
            for (int i = 0; i < 4; i++) xa[i] = Xs[k][ty * 4 + i];
#pragma unroll
            for (int j = 0; j < 4; j++) wb_[j] = Ws[tx * 4 + j][k];
#pragma unroll
            for (int i = 0; i < 4; i++)
#pragma unroll
                for (int j = 0; j < 4; j++) acc[i][j] += xa[i] * wb_[j];
        }
        __syncthreads();
    }

    // route to q/k/v. Each 64-wide o-tile is exactly one head of one region.
    int hy = blockIdx.y;
    float* dst;
    float sc = 1.0f;
    if (hy < 8)       { dst = g_q; sc = SCALE; }
    else if (hy < 16) { dst = g_k; hy -= 8; }
    else              { dst = g_v; hy -= 16; }

    float bb[4];
#pragma unroll
    for (int j = 0; j < 4; j++) bb[j] = bias[oT + tx * 4 + j];

    float* base = dst + ((size_t)(b * NHEAD + hy) * NTOK) * 64 + tx * 4;
#pragma unroll
    for (int i = 0; i < 4; i++) {
        int n = nT + ty * 4 + i;
        float4 v;
        v.x = (acc[i][0] + bb[0]) * sc;
        v.y = (acc[i][1] + bb[1]) * sc;
        v.z = (acc[i][2] + bb[2]) * sc;
        v.w = (acc[i][3] + bb[3]) * sc;
        *reinterpret_cast<float4*>(base + (size_t)n * 64) = v;
    }
}

// ---------------------------------------------------------------------------
// Kernel 2: causal flash attention, fp32.
// One block per (q-tile of 64, head, batch). 256 threads.
// Online softmax; 4x4 register micro-tiles for S=QK^T and O+=PV.
// ---------------------------------------------------------------------------
__global__ void attn_kernel()
{
    extern __shared__ float sm[];
    const int LD = 65;
    float* Qs  = sm;
    float* Ks  = Qs + 64 * LD;
    float* Vs  = Ks + 64 * LD;
    float* Ss  = Vs + 64 * LD;
    float* m_s = Ss + 64 * LD;  // [64]
    float* l_s = m_s + 64;      // [64]
    float* a_s = l_s + 64;      // [64]

    const int t  = threadIdx.x;
    const int qt = blockIdx.x;
    const int h  = blockIdx.y;
    const int b  = blockIdx.z;

    const size_t base = (size_t)(b * NHEAD + h) * NTOK * 64;
    const float* Qg = g_q + base + (size_t)qt * 64 * 64;
    const float* Kg = g_k + base;
    const float* Vg = g_v + base;

    // load Q tile
#pragma unroll
    for (int i = 0; i < 16; i++) {
        int idx = t + i * 256;
        int r = idx >> 6, c = idx & 63;
        Qs[r * LD + c] = Qg[r * 64 + c];
    }
    if (t < 64) { m_s[t] = -1e30f; l_s[t] = 0.f; }

    float acc[4][4];
#pragma unroll
    for (int i = 0; i < 4; i++)
#pragma unroll
        for (int j = 0; j < 4; j++) acc[i][j] = 0.f;

    const int r0 = (t >> 4) * 4;   // micro-tile q rows
    const int c0 = (t & 15) * 4;   // micro-tile cols (keys / v-dims)
    const int sr = t >> 2;         // softmax row
    const int sq = t & 3;          // softmax quarter (16 cols)

    __syncthreads();

    for (int kt = 0; kt <= qt; kt++) {
        const float* kg = Kg + (size_t)kt * 64 * 64;
        const float* vg = Vg + (size_t)kt * 64 * 64;
#pragma unroll
        for (int i = 0; i < 16; i++) {
            int idx = t + i * 256;
            int r = idx >> 6, c = idx & 63;
            Ks[r * LD + c] = kg[r * 64 + c];
            Vs[r * LD + c] = vg[r * 64 + c];
        }
        __syncthreads();

        // ---- S = Q K^T tile (4x4 micro) ----
        float sv[4][4];
#pragma unroll
        for (int i = 0; i < 4; i++)
#pragma unroll
            for (int j = 0; j < 4; j++) sv[i][j] = 0.f;
#pragma unroll
        for (int d = 0; d < 64; d++) {
            float qv[4], kv[4];
#pragma unroll
            for (int i = 0; i < 4; i++) qv[i] = Qs[(r0 + i) * LD + d];
#pragma unroll
            for (int j = 0; j < 4; j++) kv[j] = Ks[(c0 + j) * LD + d];
#pragma unroll
            for (int i = 0; i < 4; i++)
#pragma unroll
                for (int j = 0; j < 4; j++) sv[i][j] += qv[i] * kv[j];
        }
        const bool diag = (kt == qt);
#pragma unroll
        for (int i = 0; i < 4; i++)
#pragma unroll
            for (int j = 0; j < 4; j++) {
                float val = sv[i][j];
                if (diag && (c0 + j) > (r0 + i)) val = -1e30f;
                Ss[(r0 + i) * LD + c0 + j] = val;
            }
        __syncthreads();

        // ---- online softmax (4 lanes per row) ----
        {
            float vals[16];
            float mloc = -1e30f;
#pragma unroll
            for (int jj = 0; jj < 16; jj++) {
                vals[jj] = Ss[sr * LD + sq * 16 + jj];
                mloc = fmaxf(mloc, vals[jj]);
            }
            mloc = fmaxf(mloc, __shfl_xor_sync(0xffffffffu, mloc, 1));
            mloc = fmaxf(mloc, __shfl_xor_sync(0xffffffffu, mloc, 2));
            float mprev = m_s[sr];
            float mnew  = fmaxf(mprev, mloc);
            float ssum = 0.f;
#pragma unroll
            for (int jj = 0; jj < 16; jj++) {
                float p = __expf(vals[jj] - mnew);
                Ss[sr * LD + sq * 16 + jj] = p;
                ssum += p;
            }
            ssum += __shfl_xor_sync(0xffffffffu, ssum, 1);
            ssum += __shfl_xor_sync(0xffffffffu, ssum, 2);
            if (sq == 0) {
                float alpha = __expf(mprev - mnew);  // 0 on first tile
                m_s[sr] = mnew;
                l_s[sr] = l_s[sr] * alpha + ssum;
                a_s[sr] = alpha;
            }
        }
        __syncthreads();

        // ---- O = O*alpha + P V (4x4 micro) ----
        float al[4];
#pragma unroll
        for (int i = 0; i < 4; i++) al[i] = a_s[r0 + i];
#pragma unroll
        for (int i = 0; i < 4; i++)
#pragma unroll
            for (int j = 0; j < 4; j++) acc[i][j] *= al[i];

#pragma unroll
        for (int k = 0; k < 64; k++) {
            float pv[4], vv[4];
#pragma unroll
            for (int i = 0; i < 4; i++) pv[i] = Ss[(r0 + i) * LD + k];
#pragma unroll
            for (int j = 0; j < 4; j++) vv[j] = Vs[k * LD + c0 + j];
#pragma unroll
            for (int i = 0; i < 4; i++)
#pragma unroll
                for (int j = 0; j < 4; j++) acc[i][j] += pv[i] * vv[j];
        }
        __syncthreads();   // protect Ks/Vs/Ss before next iter
    }

    // finalize + write [b,h,n,d]
    float* Og = g_o + base + (size_t)qt * 64 * 64;
#pragma unroll
    for (int i = 0; i < 4; i++) {
        float linv = 1.f / l_s[r0 + i];
        float4 v;
        v.x = acc[i][0] * linv;
        v.y = acc[i][1] * linv;
        v.z = acc[i][2] * linv;
        v.w = acc[i][3] * linv;
        *reinterpret_cast<float4*>(Og + (size_t)(r0 + i) * 64 + c0) = v;
    }
}

// ---------------------------------------------------------------------------
// Kernel 3: projection GEMM. out[b,o,n] = sum_v pw[o,v]*O[b,h(v),n,d(v)] + pb[o]
// Tile 64(o) x 64(n) x 32(v). acc[i][j]: i -> o (ty), j -> n (tx) so n is
// thread-fast -> coalesced float4 output stores.
// ---------------------------------------------------------------------------
__global__ void proj_gemm_kernel(const float* __restrict__ pw,
                                 const float* __restrict__ pb,
                                 float* __restrict__ out)
{
    __shared__ float Ws[64][33];   // [o][v]
    __shared__ float Os[32][64];   // [v][n]

    const int b  = blockIdx.z;
    const int oT = blockIdx.y * 64;
    const int nT = blockIdx.x * 64;
    const int t  = threadIdx.x;
    const int tx = t & 15;
    const int ty = t >> 4;

    float acc[4][4];
#pragma unroll
    for (int i = 0; i < 4; i++)
#pragma unroll
        for (int j = 0; j < 4; j++) acc[i][j] = 0.f;

    const int wk  = t & 31, wr0 = t >> 5;
    const int ok  = t & 31, oc0 = t >> 5;

    for (int kk = 0; kk < NHEAD * DV; kk += 32) {
#pragma unroll
        for (int i = 0; i < 8; i++) {
            int r = wr0 + i * 8;
            Ws[r][wk] = pw[(size_t)(oT + r) * (NHEAD * DV) + kk + wk];
        }
        // g_o is [b,h,n,d]; v = kk + k, h = v>>6, d = v&63 (kk mult of 32 -> one head)
        {
            const int hh = kk >> 6, d0 = kk & 63;
            const float* og = g_o + ((size_t)(b * NHEAD + hh) * NTOK + nT) * 64 + d0;
#pragma unroll
            for (int i = 0; i < 8; i++) {
                int c = oc0 + i * 8;
                Os[ok][c] = og[(size_t)c * 64 + ok];
            }
        }
        __syncthreads();

#pragma unroll
        for (int k = 0; k < 32; k++) {
            float wa[4], ob[4];
#pragma unroll
            for (int i = 0; i < 4; i++) wa[i] = Ws[ty * 4 + i][k];
#pragma unroll
            for (int j = 0; j < 4; j++) ob[j] = Os[k][tx * 4 + j];
#pragma unroll
            for (int i = 0; i < 4; i++)
#pragma unroll
                for (int j = 0; j < 4; j++) acc[i][j] += wa[i] * ob[j];
        }
        __syncthreads();
    }

#pragma unroll
    for (int i = 0; i < 4; i++) {
        int o = oT + ty * 4 + i;
        float bi = pb[o];
        float4 v;
        v.x = acc[i][0] + bi;
        v.y = acc[i][1] + bi;
        v.z = acc[i][2] + bi;
        v.w = acc[i][3] + bi;
        *reinterpret_cast<float4*>(out + ((size_t)b * 256 + o) * NTOK + nT + tx * 4) = v;
    }
}

// ---------------------------------------------------------------------------
extern "C" void kernel_launch(void* const* d_in, const int* in_sizes, int n_in,
                              void* d_out, int out_size)
{
    const float* x      = (const float*)d_in[0];
    const float* qkv_w  = (const float*)d_in[1];
    const float* qkv_b  = (const float*)d_in[2];
    const float* proj_w = (const float*)d_in[3];
    const float* proj_b = (const float*)d_in[4];
    float* out = (float*)d_out;

    const int attn_smem = (4 * 64 * 65 + 3 * 64) * (int)sizeof(float);  // 67328 B
    cudaFuncSetAttribute(attn_kernel, cudaFuncAttributeMaxDynamicSharedMemorySize,
                         attn_smem);

    qkv_gemm_kernel<<<dim3(16, 24, BATCH), 256>>>(x, qkv_w, qkv_b);
    attn_kernel<<<dim3(16, NHEAD, BATCH), 256, attn_smem>>>();
    proj_gemm_kernel<<<dim3(16, 4, BATCH), 256>>>(proj_w, proj_b, out);
}

// round 2
// speedup vs baseline: 2.0461x; 2.0461x over previous
#include <cuda_runtime.h>
#include <cuda_bf16.h>

#define BATCH   16
#define IN_CH   256
#define NTOK    1024
#define NHEAD   8
#define SCALE   0.125f

// Scratch: [B, H, N, D]
__device__ __align__(16) float g_q[BATCH * NHEAD * NTOK * 64];
__device__ __align__(16) float g_k[BATCH * NHEAD * NTOK * 64];
__device__ __align__(16) float g_v[BATCH * NHEAD * NTOK * 64];
__device__ __align__(16) float g_o[BATCH * NHEAD * NTOK * 64];

__device__ __forceinline__ unsigned f2tf(float f) {
    unsigned u;
    asm("cvt.rna.tf32.f32 %0, %1;" : "=r"(u) : "f"(f));
    return u;
}

__device__ __forceinline__ void mma8(float* d, const unsigned* a, const unsigned* b) {
    asm volatile(
        "mma.sync.aligned.m16n8k8.row.col.f32.tf32.tf32.f32 "
        "{%0,%1,%2,%3}, {%4,%5,%6,%7}, {%8,%9}, {%0,%1,%2,%3};\n"
        : "+f"(d[0]), "+f"(d[1]), "+f"(d[2]), "+f"(d[3])
        : "r"(a[0]), "r"(a[1]), "r"(a[2]), "r"(a[3]), "r"(b[0]), "r"(b[1]));
}

// ---------------------------------------------------------------------------
// Kernel 1: QKV GEMM. C[token m, chan o] = sum_c x[b,c,m] * w[o,c]
// Block tile 64m x 128n, BK=16, 8 warps (2m x 4n), warp tile 32x32.
// A smem [k][m] ld72 (transposed store: gmem is [c][n] -> contiguous m).
// B smem [n][k] ld72.
// ---------------------------------------------------------------------------
__global__ void qkv_gemm_kernel(const float* __restrict__ x,
                                const float* __restrict__ w,
                                const float* __restrict__ bias)
{
    __shared__ unsigned As[16 * 72];
    __shared__ unsigned Bs[128 * 72];

    const int b  = blockIdx.z;
    const int mT = blockIdx.x * 64;
    const int nT = blockIdx.y * 128;
    const int t = threadIdx.x;
    const int lane = t & 31;
    const int warp = t >> 5;
    const int wm = (warp & 1) * 32;
    const int wn = (warp >> 1) * 32;
    const int lr = lane >> 2;
    const int lc = lane & 3;

    const float* xb = x + (size_t)b * (IN_CH * NTOK);

    float acc[2][4][4];
#pragma unroll
    for (int i = 0; i < 2; i++)
#pragma unroll
        for (int j = 0; j < 4; j++)
#pragma unroll
            for (int q = 0; q < 4; q++) acc[i][j][q] = 0.f;

    const int am = t & 63, ak = t >> 6;
    const int bn = t >> 2, bk = (t & 3) * 4;

    for (int kk = 0; kk < IN_CH; kk += 16) {
#pragma unroll
        for (int i = 0; i < 4; i++) {
            int k = ak + i * 4;
            As[k * 72 + am] = f2tf(xb[(size_t)(kk + k) * NTOK + mT + am]);
        }
#pragma unroll
        for (int i = 0; i < 2; i++) {
            int n = bn + i * 64;
            float4 v = *reinterpret_cast<const float4*>(w + (size_t)(nT + n) * IN_CH + kk + bk);
            unsigned* d = &Bs[n * 72 + bk];
            d[0] = f2tf(v.x); d[1] = f2tf(v.y); d[2] = f2tf(v.z); d[3] = f2tf(v.w);
        }
        __syncthreads();
#pragma unroll
        for (int ks = 0; ks < 16; ks += 8) {
            unsigned a[2][4], bb[4][2];
#pragma unroll
            for (int mi = 0; mi < 2; mi++) {
                const unsigned* p = &As[(ks + lc) * 72 + wm + mi * 16 + lr];
                a[mi][0] = p[0];
                a[mi][1] = p[8];
                a[mi][2] = p[4 * 72];
                a[mi][3] = p[4 * 72 + 8];
            }
#pragma unroll
            for (int ni = 0; ni < 4; ni++) {
                const unsigned* p = &Bs[(wn + ni * 8 + lr) * 72 + ks + lc];
                bb[ni][0] = p[0];
                bb[ni][1] = p[4];
            }
#pragma unroll
            for (int mi = 0; mi < 2; mi++)
#pragma unroll
                for (int ni = 0; ni < 4; ni++)
                    mma8(acc[mi][ni], a[mi], bb[ni]);
        }
        __syncthreads();
    }

    // epilogue: scatter to g_q/g_k/g_v [b,h,token,d]; q pre-scaled
#pragma unroll
    for (int ni = 0; ni < 4; ni++) {
        int o = nT + wn + ni * 8 + 2 * lc;
        float* dst;
        float sc = 1.f;
        if (o < 512)       { dst = g_q; sc = SCALE; }
        else if (o < 1024) { dst = g_k; }
        else               { dst = g_v; }
        int head = (o >> 6) & 7;
        int d = o & 63;
        float b0 = bias[o], b1 = bias[o + 1];
        float* base = dst + ((size_t)(b * NHEAD + head) * NTOK) * 64 + d;
#pragma unroll
        for (int mi = 0; mi < 2; mi++) {
            int r = mT + wm + mi * 16 + lr;
            *reinterpret_cast<float2*>(base + (size_t)r * 64) =
                make_float2((acc[mi][ni][0] + b0) * sc, (acc[mi][ni][1] + b1) * sc);
            *reinterpret_cast<float2*>(base + (size_t)(r + 8) * 64) =
                make_float2((acc[mi][ni][2] + b0) * sc, (acc[mi][ni][3] + b1) * sc);
        }
    }
}

// ---------------------------------------------------------------------------
// Kernel 2: causal flash attention with tf32 mma.
// Block per (qtile 64, head, batch). 8 warps (2m x 4n), warp tile 32x16.
// ---------------------------------------------------------------------------
__global__ void attn_kernel()
{
    extern __shared__ unsigned sm[];
    unsigned* Qs = sm;             // [m][d]   ld72
    unsigned* Ks = Qs + 64 * 72;   // [key][d] ld72
    unsigned* Vs = Ks + 64 * 72;   // [key][dv]ld72
    unsigned* Ps = Vs + 64 * 72;   // S(float) then P(tf32)
    float* Sf  = (float*)Ps;
    float* m_s = (float*)(Ps + 64 * 72);
    float* l_s = m_s + 64;
    float* a_s = l_s + 64;

    const int t = threadIdx.x, lane = t & 31, warp = t >> 5;
    const int wm = (warp & 1) * 32;
    const int wn = (warp >> 1) * 16;
    const int lr = lane >> 2, lc = lane & 3;
    const int qt = blockIdx.x, h = blockIdx.y, b = blockIdx.z;

    const size_t base = (size_t)(b * NHEAD + h) * (NTOK * 64);
    const float* Qg = g_q + base + (size_t)qt * 4096;
    const float* Kg = g_k + base;
    const float* Vg = g_v + base;

    const int lrow = t >> 4, lcol = (t & 15) * 4;
#pragma unroll
    for (int i = 0; i < 4; i++) {
        int r = lrow + i * 16;
        float4 v = *reinterpret_cast<const float4*>(Qg + r * 64 + lcol);
        unsigned* d = &Qs[r * 72 + lcol];
        d[0] = f2tf(v.x); d[1] = f2tf(v.y); d[2] = f2tf(v.z); d[3] = f2tf(v.w);
    }
    if (t < 64) { m_s[t] = -1e30f; l_s[t] = 0.f; }

    float oacc[2][2][4];
#pragma unroll
    for (int i = 0; i < 2; i++)
#pragma unroll
        for (int j = 0; j < 2; j++)
#pragma unroll
            for (int q = 0; q < 4; q++) oacc[i][j][q] = 0.f;

    const int sr = t >> 2, sq = t & 3;
    __syncthreads();

    for (int kt = 0; kt <= qt; kt++) {
        const float* kg = Kg + (size_t)kt * 4096;
        const float* vg = Vg + (size_t)kt * 4096;
#pragma unroll
        for (int i = 0; i < 4; i++) {
            int r = lrow + i * 16;
            float4 kv = *reinterpret_cast<const float4*>(kg + r * 64 + lcol);
            float4 vv = *reinterpret_cast<const float4*>(vg + r * 64 + lcol);
            unsigned* dk = &Ks[r * 72 + lcol];
            dk[0] = f2tf(kv.x); dk[1] = f2tf(kv.y); dk[2] = f2tf(kv.z); dk[3] = f2tf(kv.w);
            unsigned* dv = &Vs[r * 72 + lcol];
            dv[0] = f2tf(vv.x); dv[1] = f2tf(vv.y); dv[2] = f2tf(vv.z); dv[3] = f2tf(vv.w);
        }
        __syncthreads();

        // ---- S = Q K^T ----
        float s[2][2][4];
#pragma unroll
        for (int i = 0; i < 2; i++)
#pragma unroll
            for (int j = 0; j < 2; j++)
#pragma unroll
                for (int q = 0; q < 4; q++) s[i][j][q] = 0.f;
#pragma unroll
        for (int ks = 0; ks < 64; ks += 8) {
            unsigned a[2][4], bb[2][2];
#pragma unroll
            for (int mi = 0; mi < 2; mi++) {
                const unsigned* p = &Qs[(wm + mi * 16 + lr) * 72 + ks + lc];
                a[mi][0] = p[0]; a[mi][1] = p[8 * 72]; a[mi][2] = p[4]; a[mi][3] = p[8 * 72 + 4];
            }
#pragma unroll
            for (int ni = 0; ni < 2; ni++) {
                const unsigned* p = &Ks[(wn + ni * 8 + lr) * 72 + ks + lc];
                bb[ni][0] = p[0]; bb[ni][1] = p[4];
            }
#pragma unroll
            for (int mi = 0; mi < 2; mi++)
#pragma unroll
                for (int ni = 0; ni < 2; ni++)
                    mma8(s[mi][ni], a[mi], bb[ni]);
        }
        const bool diag = (kt == qt);
#pragma unroll
        for (int mi = 0; mi < 2; mi++)
#pragma unroll
            for (int ni = 0; ni < 2; ni++) {
                int r = wm + mi * 16 + lr;
                int c = wn + ni * 8 + 2 * lc;
                float v0 = s[mi][ni][0], v1 = s[mi][ni][1];
                float v2 = s[mi][ni][2], v3 = s[mi][ni][3];
                if (diag) {
                    if (c > r) v0 = -1e30f;
                    if (c + 1 > r) v1 = -1e30f;
                    if (c > r + 8) v2 = -1e30f;
                    if (c + 1 > r + 8) v3 = -1e30f;
                }
                *reinterpret_cast<float2*>(&Sf[r * 72 + c]) = make_float2(v0, v1);
                *reinterpret_cast<float2*>(&Sf[(r + 8) * 72 + c]) = make_float2(v2, v3);
            }
        __syncthreads();

        // ---- online softmax (4 lanes per row), write P as tf32 ----
        {
            float vals[16];
            float mloc = -1e30f;
#pragma unroll
            for (int j = 0; j < 16; j++) {
                vals[j] = Sf[sr * 72 + sq * 16 + j];
                mloc = fmaxf(mloc, vals[j]);
            }
            mloc = fmaxf(mloc, __shfl_xor_sync(0xffffffffu, mloc, 1));
            mloc = fmaxf(mloc, __shfl_xor_sync(0xffffffffu, mloc, 2));
            float mprev = m_s[sr];
            float mnew  = fmaxf(mprev, mloc);
            float ssum = 0.f;
#pragma unroll
            for (int j = 0; j < 16; j++) {
                float p = __expf(vals[j] - mnew);
                ssum += p;
                Ps[sr * 72 + sq * 16 + j] = f2tf(p);
            }
            ssum += __shfl_xor_sync(0xffffffffu, ssum, 1);
            ssum += __shfl_xor_sync(0xffffffffu, ssum, 2);
            if (sq == 0) {
                float alpha = __expf(mprev - mnew);
                m_s[sr] = mnew;
                l_s[sr] = l_s[sr] * alpha + ssum;
                a_s[sr] = alpha;
            }
        }
        __syncthreads();

        // ---- O = O*alpha + P V ----
#pragma unroll
        for (int mi = 0; mi < 2; mi++) {
            float al0 = a_s[wm + mi * 16 + lr];
            float al1 = a_s[wm + mi * 16 + lr + 8];
#pragma unroll
            for (int ni = 0; ni < 2; ni++) {
                oacc[mi][ni][0] *= al0; oacc[mi][ni][1] *= al0;
                oacc[mi][ni][2] *= al1; oacc[mi][ni][3] *= al1;
            }
        }
#pragma unroll
        for (int ks = 0; ks < 64; ks += 8) {
            unsigned a[2][4], bb[2][2];
#pragma unroll
            for (int mi = 0; mi < 2; mi++) {
                const unsigned* p = &Ps[(wm + mi * 16 + lr) * 72 + ks + lc];
                a[mi][0] = p[0]; a[mi][1] = p[8 * 72]; a[mi][2] = p[4]; a[mi][3] = p[8 * 72 + 4];
            }
#pragma unroll
            for (int ni = 0; ni < 2; ni++) {
                const unsigned* p = &Vs[(ks + lc) * 72 + wn + ni * 8 + lr];
                bb[ni][0] = p[0]; bb[ni][1] = p[4 * 72];
            }
#pragma unroll
            for (int mi = 0; mi < 2; mi++)
#pragma unroll
                for (int ni = 0; ni < 2; ni++)
                    mma8(oacc[mi][ni], a[mi], bb[ni]);
        }
        __syncthreads();
    }

    // finalize
    float* Og = g_o + base + (size_t)qt * 4096;
#pragma unroll
    for (int mi = 0; mi < 2; mi++) {
        int r = wm + mi * 16 + lr;
        float li0 = 1.f / l_s[r];
        float li1 = 1.f / l_s[r + 8];
#pragma unroll
        for (int ni = 0; ni < 2; ni++) {
            int c = wn + ni * 8 + 2 * lc;
            *reinterpret_cast<float2*>(Og + r * 64 + c) =
                make_float2(oacc[mi][ni][0] * li0, oacc[mi][ni][1] * li0);
            *reinterpret_cast<float2*>(Og + (r + 8) * 64 + c) =
                make_float2(oacc[mi][ni][2] * li1, oacc[mi][ni][3] * li1);
        }
    }
}

// ---------------------------------------------------------------------------
// Kernel 3: proj GEMM. out[b, o, token] = sum_v pw[o,v]*O[b,h(v),token,d(v)]
// Block tile 64m(token) x 128n(o), BK=16, K=512. Smem transpose epilogue.
// ---------------------------------------------------------------------------
__global__ void proj_gemm_kernel(const float* __restrict__ pw,
                                 const float* __restrict__ pb,
                                 float* __restrict__ out)
{
    __shared__ unsigned smem[64 * 72 + 128 * 72];
    unsigned* As = smem;            // [m][k] ld72
    unsigned* Bs = smem + 64 * 72;  // [n][k] ld72

    const int b  = blockIdx.z;
    const int mT = blockIdx.x * 64;
    const int nT = blockIdx.y * 128;
    const int t = threadIdx.x;
    const int lane = t & 31;
    const int warp = t >> 5;
    const int wm = (warp & 1) * 32;
    const int wn = (warp >> 1) * 32;
    const int lr = lane >> 2;
    const int lc = lane & 3;

    float acc[2][4][4];
#pragma unroll
    for (int i = 0; i < 2; i++)
#pragma unroll
        for (int j = 0; j < 4; j++)
#pragma unroll
            for (int q = 0; q < 4; q++) acc[i][j][q] = 0.f;

    const int am = t >> 2, ak4 = (t & 3) * 4;
    const int bn = t >> 2, bk4 = (t & 3) * 4;

    for (int kk = 0; kk < 512; kk += 16) {
        {
            int head = kk >> 6;
            int d0 = (kk & 63) + ak4;
            float4 v = *reinterpret_cast<const float4*>(
                g_o + ((size_t)(b * NHEAD + head) * NTOK + mT + am) * 64 + d0);
            unsigned* d = &As[am * 72 + ak4];
            d[0] = f2tf(v.x); d[1] = f2tf(v.y); d[2] = f2tf(v.z); d[3] = f2tf(v.w);
        }
#pragma unroll
        for (int i = 0; i < 2; i++) {
            int n = bn + i * 64;
            float4 v = *reinterpret_cast<const float4*>(pw + (size_t)(nT + n) * 512 + kk + bk4);
            unsigned* d = &Bs[n * 72 + bk4];
            d[0] = f2tf(v.x); d[1] = f2tf(v.y); d[2] = f2tf(v.z); d[3] = f2tf(v.w);
        }
        __syncthreads();
#pragma unroll
        for (int ks = 0; ks < 16; ks += 8) {
            unsigned a[2][4], bb[4][2];
#pragma unroll
            for (int mi = 0; mi < 2; mi++) {
                const unsigned* p = &As[(wm + mi * 16 + lr) * 72 + ks + lc];
                a[mi][0] = p[0]; a[mi][1] = p[8 * 72]; a[mi][2] = p[4]; a[mi][3] = p[8 * 72 + 4];
            }
#pragma unroll
            for (int ni = 0; ni < 4; ni++) {
                const unsigned* p = &Bs[(wn + ni * 8 + lr) * 72 + ks + lc];
                bb[ni][0] = p[0]; bb[ni][1] = p[4];
            }
#pragma unroll
            for (int mi = 0; mi < 2; mi++)
#pragma unroll
                for (int ni = 0; ni < 4; ni++)
                    mma8(acc[mi][ni], a[mi], bb[ni]);
        }
        __syncthreads();
    }

    // transpose epilogue through smem: Cs[n][m] ld68
    float* Cs = (float*)smem;
#pragma unroll
    for (int ni = 0; ni < 4; ni++) {
        int n = wn + ni * 8 + 2 * lc;
#pragma unroll
        for (int mi = 0; mi < 2; mi++) {
            int m = wm + mi * 16 + lr;
            Cs[n * 68 + m]           = acc[mi][ni][0];
            Cs[(n + 1) * 68 + m]     = acc[mi][ni][1];
            Cs[n * 68 + m + 8]       = acc[mi][ni][2];
            Cs[(n + 1) * 68 + m + 8] = acc[mi][ni][3];
        }
    }
    __syncthreads();

    const int wrn = t >> 4, wrc = (t & 15) * 4;
#pragma unroll
    for (int i = 0; i < 8; i++) {
        int n = wrn + i * 16;
        float bi = pb[nT + n];
        const float* src = &Cs[n * 68 + wrc];
        float4 v;
        v.x = src[0] + bi; v.y = src[1] + bi; v.z = src[2] + bi; v.w = src[3] + bi;
        *reinterpret_cast<float4*>(out + (size_t)(b * 256 + nT + n) * NTOK + mT + wrc) = v;
    }
}

// ---------------------------------------------------------------------------
extern "C" void kernel_launch(void* const* d_in, const int* in_sizes, int n_in,
                              void* d_out, int out_size)
{
    const float* x      = (const float*)d_in[0];
    const float* qkv_w  = (const float*)d_in[1];
    const float* qkv_b  = (const float*)d_in[2];
    const float* proj_w = (const float*)d_in[3];
    const float* proj_b = (const float*)d_in[4];
    float* out = (float*)d_out;

    const int attn_smem = (4 * 64 * 72 + 3 * 64) * (int)sizeof(float);  // 74496 B
    cudaFuncSetAttribute(attn_kernel, cudaFuncAttributeMaxDynamicSharedMemorySize,
                         attn_smem);

    qkv_gemm_kernel<<<dim3(16, 12, BATCH), 256>>>(x, qkv_w, qkv_b);
    attn_kernel<<<dim3(16, NHEAD, BATCH), 256, attn_smem>>>();
    proj_gemm_kernel<<<dim3(16, 2, BATCH), 256>>>(proj_w, proj_b, out);
}

// round 3
// speedup vs baseline: 2.6379x; 1.2893x over previous
#include <cuda_runtime.h>
#include <cuda_bf16.h>

#define BATCH   16
#define IN_CH   256
#define NTOK    1024
#define NHEAD   8
#define SCALE   0.125f

// Scratch: [B, H, N, D]
__device__ __align__(16) float g_q[BATCH * NHEAD * NTOK * 64];
__device__ __align__(16) float g_k[BATCH * NHEAD * NTOK * 64];
__device__ __align__(16) float g_v[BATCH * NHEAD * NTOK * 64];
__device__ __align__(16) float g_o[BATCH * NHEAD * NTOK * 64];

__device__ __forceinline__ unsigned f2tf(float f) {
    unsigned u;
    asm("cvt.rna.tf32.f32 %0, %1;" : "=r"(u) : "f"(f));
    return u;
}

__device__ __forceinline__ void mma8(float* d, const unsigned* a, const unsigned* b) {
    asm volatile(
        "mma.sync.aligned.m16n8k8.row.col.f32.tf32.tf32.f32 "
        "{%0,%1,%2,%3}, {%4,%5,%6,%7}, {%8,%9}, {%0,%1,%2,%3};\n"
        : "+f"(d[0]), "+f"(d[1]), "+f"(d[2]), "+f"(d[3])
        : "r"(a[0]), "r"(a[1]), "r"(a[2]), "r"(a[3]), "r"(b[0]), "r"(b[1]));
}

__device__ __forceinline__ uint4 f2tf4(float4 v) {
    uint4 u;
    u.x = f2tf(v.x); u.y = f2tf(v.y); u.z = f2tf(v.z); u.w = f2tf(v.w);
    return u;
}

// ---------------------------------------------------------------------------
// Kernel 1: QKV GEMM. C[token m, chan o] = sum_c x[b,c,m] * w[o,c]
// Block 128m x 128n, BK=16, 8 warps (2m x 4n), warp tile 64x32.
// Double-buffered smem. As [k][m] ld136 (col-major A), Bs [n][k] ld40.
// ---------------------------------------------------------------------------
__global__ void qkv_gemm_kernel(const float* __restrict__ x,
                                const float* __restrict__ w,
                                const float* __restrict__ bias)
{
    extern __shared__ unsigned smem[];
    unsigned* As = smem;            // [2][16][136]
    unsigned* Bs = smem + 4352;     // [2][128][40]

    const int b  = blockIdx.z;
    const int mT = blockIdx.x * 128;
    const int nT = blockIdx.y * 128;
    const int t = threadIdx.x;
    const int lane = t & 31;
    const int warp = t >> 5;
    const int wm = (warp & 1) * 64;
    const int wn = (warp >> 1) * 32;
    const int lr = lane >> 2;
    const int lc = lane & 3;

    const float* xb = x + (size_t)b * (IN_CH * NTOK);

    float acc[4][4][4];
#pragma unroll
    for (int i = 0; i < 4; i++)
#pragma unroll
        for (int j = 0; j < 4; j++)
#pragma unroll
            for (int q = 0; q < 4; q++) acc[i][j][q] = 0.f;

    const int a_m = (t & 31) * 4, a_k = t >> 5;
    const int b_n = t >> 2,       b_k = (t & 3) * 4;

    float4 ax[2], bx[2];
    // prologue: kk = 0
#pragma unroll
    for (int i = 0; i < 2; i++)
        ax[i] = *reinterpret_cast<const float4*>(xb + (size_t)(a_k + i * 8) * NTOK + mT + a_m);
#pragma unroll
    for (int i = 0; i < 2; i++)
        bx[i] = *reinterpret_cast<const float4*>(w + (size_t)(nT + b_n + i * 64) * IN_CH + b_k);
    {
        unsigned* Ab = As;
        unsigned* Bb = Bs;
#pragma unroll
        for (int i = 0; i < 2; i++)
            *reinterpret_cast<uint4*>(&Ab[(a_k + i * 8) * 136 + a_m]) = f2tf4(ax[i]);
#pragma unroll
        for (int i = 0; i < 2; i++)
            *reinterpret_cast<uint4*>(&Bb[(b_n + i * 64) * 40 + b_k]) = f2tf4(bx[i]);
    }
    __syncthreads();

    for (int it = 0; it < 16; it++) {
        const unsigned* Ac = As + (it & 1) * 2176;
        const unsigned* Bc = Bs + (it & 1) * 5120;
        if (it < 15) {
            int kk = (it + 1) * 16;
#pragma unroll
            for (int i = 0; i < 2; i++)
                ax[i] = *reinterpret_cast<const float4*>(xb + (size_t)(kk + a_k + i * 8) * NTOK + mT + a_m);
#pragma unroll
            for (int i = 0; i < 2; i++)
                bx[i] = *reinterpret_cast<const float4*>(w + (size_t)(nT + b_n + i * 64) * IN_CH + kk + b_k);
        }
#pragma unroll
        for (int ks = 0; ks < 16; ks += 8) {
            unsigned a[4][4], bb[4][2];
#pragma unroll
            for (int mi = 0; mi < 4; mi++) {
                const unsigned* p = &Ac[(ks + lc) * 136 + wm + mi * 16 + lr];
                a[mi][0] = p[0]; a[mi][1] = p[8]; a[mi][2] = p[544]; a[mi][3] = p[552];
            }
#pragma unroll
            for (int ni = 0; ni < 4; ni++) {
                const unsigned* p = &Bc[(wn + ni * 8 + lr) * 40 + ks + lc];
                bb[ni][0] = p[0]; bb[ni][1] = p[4];
            }
#pragma unroll
            for (int mi = 0; mi < 4; mi++)
#pragma unroll
                for (int ni = 0; ni < 4; ni++)
                    mma8(acc[mi][ni], a[mi], bb[ni]);
        }
        if (it < 15) {
            unsigned* Ab = As + ((it + 1) & 1) * 2176;
            unsigned* Bb = Bs + ((it + 1) & 1) * 5120;
#pragma unroll
            for (int i = 0; i < 2; i++)
                *reinterpret_cast<uint4*>(&Ab[(a_k + i * 8) * 136 + a_m]) = f2tf4(ax[i]);
#pragma unroll
            for (int i = 0; i < 2; i++)
                *reinterpret_cast<uint4*>(&Bb[(b_n + i * 64) * 40 + b_k]) = f2tf4(bx[i]);
        }
        __syncthreads();
    }

    // epilogue: scatter to g_q/g_k/g_v [b,h,token,d]; q pre-scaled
#pragma unroll
    for (int ni = 0; ni < 4; ni++) {
        int o = nT + wn + ni * 8 + 2 * lc;
        float* dst;
        float sc = 1.f;
        if (o < 512)       { dst = g_q; sc = SCALE; }
        else if (o < 1024) { dst = g_k; }
        else               { dst = g_v; }
        int head = (o >> 6) & 7;
        int d = o & 63;
        float b0 = bias[o], b1 = bias[o + 1];
        float* base = dst + ((size_t)(b * NHEAD + head) * NTOK) * 64 + d;
#pragma unroll
        for (int mi = 0; mi < 4; mi++) {
            int r = mT + wm + mi * 16 + lr;
            *reinterpret_cast<float2*>(base + (size_t)r * 64) =
                make_float2((acc[mi][ni][0] + b0) * sc, (acc[mi][ni][1] + b1) * sc);
            *reinterpret_cast<float2*>(base + (size_t)(r + 8) * 64) =
                make_float2((acc[mi][ni][2] + b0) * sc, (acc[mi][ni][3] + b1) * sc);
        }
    }
}

// ---------------------------------------------------------------------------
// Kernel 2: causal flash attention, BM=128, BN=64.
// 8 warps (4m x 2n), warp tile 32x32. K/V register prefetch.
// ---------------------------------------------------------------------------
__global__ void attn_kernel()
{
    extern __shared__ unsigned sm[];
    unsigned* Qs = sm;              // [128][72]
    unsigned* Ks = sm + 9216;       // [64][72]
    unsigned* Vs = sm + 13824;      // [64][72]
    unsigned* Ps = sm + 18432;      // [128][72]  S(float) then P(tf32)
    float* Sf  = (float*)Ps;
    float* m_s = (float*)(sm + 27648);
    float* l_s = m_s + 128;
    float* a_s = l_s + 128;

    const int t = threadIdx.x, lane = t & 31, warp = t >> 5;
    const int wm = (warp & 3) * 32;
    const int wn = (warp >> 2) * 32;
    const int lr = lane >> 2, lc = lane & 3;
    const int qt = blockIdx.x, h = blockIdx.y, b = blockIdx.z;

    const size_t base = (size_t)(b * NHEAD + h) * (NTOK * 64);
    const float* Qg = g_q + base + (size_t)qt * 128 * 64;
    const float* Kg = g_k + base;
    const float* Vg = g_v + base;

    const int lrow = t >> 4, lcol = (t & 15) * 4;
#pragma unroll
    for (int i = 0; i < 8; i++) {
        int r = lrow + i * 16;
        float4 v = *reinterpret_cast<const float4*>(Qg + r * 64 + lcol);
        *reinterpret_cast<uint4*>(&Qs[r * 72 + lcol]) = f2tf4(v);
    }
    if (t < 128) { m_s[t] = -1e30f; l_s[t] = 0.f; }

    float oacc[2][4][4];
#pragma unroll
    for (int i = 0; i < 2; i++)
#pragma unroll
        for (int j = 0; j < 4; j++)
#pragma unroll
            for (int q = 0; q < 4; q++) oacc[i][j][q] = 0.f;

    const int sr = t >> 1, sq = t & 1;
    const int kt_last = 2 * qt + 1;

    float4 kreg[4], vreg[4];
#pragma unroll
    for (int i = 0; i < 4; i++) {
        int r = lrow + i * 16;
        kreg[i] = *reinterpret_cast<const float4*>(Kg + r * 64 + lcol);
        vreg[i] = *reinterpret_cast<const float4*>(Vg + r * 64 + lcol);
    }
    __syncthreads();

    for (int kt = 0; kt <= kt_last; kt++) {
        // store current K/V tile
#pragma unroll
        for (int i = 0; i < 4; i++) {
            int r = lrow + i * 16;
            *reinterpret_cast<uint4*>(&Ks[r * 72 + lcol]) = f2tf4(kreg[i]);
            *reinterpret_cast<uint4*>(&Vs[r * 72 + lcol]) = f2tf4(vreg[i]);
        }
        __syncthreads();
        if (kt < kt_last) {
            const float* kg = Kg + (size_t)(kt + 1) * 64 * 64;
            const float* vg = Vg + (size_t)(kt + 1) * 64 * 64;
#pragma unroll
            for (int i = 0; i < 4; i++) {
                int r = lrow + i * 16;
                kreg[i] = *reinterpret_cast<const float4*>(kg + r * 64 + lcol);
                vreg[i] = *reinterpret_cast<const float4*>(vg + r * 64 + lcol);
            }
        }

        // ---- S = Q K^T ----
        float s[2][4][4];
#pragma unroll
        for (int i = 0; i < 2; i++)
#pragma unroll
            for (int j = 0; j < 4; j++)
#pragma unroll
                for (int q = 0; q < 4; q++) s[i][j][q] = 0.f;
#pragma unroll
        for (int ks = 0; ks < 64; ks += 8) {
            unsigned a[2][4], bb[4][2];
#pragma unroll
            for (int mi = 0; mi < 2; mi++) {
                const unsigned* p = &Qs[(wm + mi * 16 + lr) * 72 + ks + lc];
                a[mi][0] = p[0]; a[mi][1] = p[576]; a[mi][2] = p[4]; a[mi][3] = p[580];
            }
#pragma unroll
            for (int ni = 0; ni < 4; ni++) {
                const unsigned* p = &Ks[(wn + ni * 8 + lr) * 72 + ks + lc];
                bb[ni][0] = p[0]; bb[ni][1] = p[4];
            }
#pragma unroll
            for (int mi = 0; mi < 2; mi++)
#pragma unroll
                for (int ni = 0; ni < 4; ni++)
                    mma8(s[mi][ni], a[mi], bb[ni]);
        }
        const bool partial = (kt >= 2 * qt);
        const int cg0 = kt * 64, rg0 = qt * 128;
#pragma unroll
        for (int mi = 0; mi < 2; mi++)
#pragma unroll
            for (int ni = 0; ni < 4; ni++) {
                int r = wm + mi * 16 + lr;
                int c = wn + ni * 8 + 2 * lc;
                float v0 = s[mi][ni][0], v1 = s[mi][ni][1];
                float v2 = s[mi][ni][2], v3 = s[mi][ni][3];
                if (partial) {
                    int rg = rg0 + r, cg = cg0 + c;
                    if (cg > rg)         v0 = -1e30f;
                    if (cg + 1 > rg)     v1 = -1e30f;
                    if (cg > rg + 8)     v2 = -1e30f;
                    if (cg + 1 > rg + 8) v3 = -1e30f;
                }
                *reinterpret_cast<float2*>(&Sf[r * 72 + c]) = make_float2(v0, v1);
                *reinterpret_cast<float2*>(&Sf[(r + 8) * 72 + c]) = make_float2(v2, v3);
            }
        __syncthreads();

        // ---- online softmax (2 lanes per row, vectorized) ----
        {
            const float4* rp = reinterpret_cast<const float4*>(&Sf[sr * 72 + sq * 32]);
            float4 v[8];
            float mloc = -1e30f;
#pragma unroll
            for (int j = 0; j < 8; j++) {
                v[j] = rp[j];
                mloc = fmaxf(mloc, fmaxf(fmaxf(v[j].x, v[j].y), fmaxf(v[j].z, v[j].w)));
            }
            mloc = fmaxf(mloc, __shfl_xor_sync(0xffffffffu, mloc, 1));
            float mprev = m_s[sr];
            float mnew  = fmaxf(mprev, mloc);
            float ssum = 0.f;
            uint4* wp = reinterpret_cast<uint4*>(&Ps[sr * 72 + sq * 32]);
#pragma unroll
            for (int j = 0; j < 8; j++) {
                float e0 = __expf(v[j].x - mnew);
                float e1 = __expf(v[j].y - mnew);
                float e2 = __expf(v[j].z - mnew);
                float e3 = __expf(v[j].w - mnew);
                ssum += (e0 + e1) + (e2 + e3);
                uint4 u;
                u.x = f2tf(e0); u.y = f2tf(e1); u.z = f2tf(e2); u.w = f2tf(e3);
                wp[j] = u;
            }
            ssum += __shfl_xor_sync(0xffffffffu, ssum, 1);
            if (sq == 0) {
                float alpha = __expf(mprev - mnew);
                m_s[sr] = mnew;
                l_s[sr] = l_s[sr] * alpha + ssum;
                a_s[sr] = alpha;
            }
        }
        __syncthreads();

        // ---- O = O*alpha + P V ----
#pragma unroll
        for (int mi = 0; mi < 2; mi++) {
            float al0 = a_s[wm + mi * 16 + lr];
            float al1 = a_s[wm + mi * 16 + lr + 8];
#pragma unroll
            for (int ni = 0; ni < 4; ni++) {
                oacc[mi][ni][0] *= al0; oacc[mi][ni][1] *= al0;
                oacc[mi][ni][2] *= al1; oacc[mi][ni][3] *= al1;
            }
        }
#pragma unroll
        for (int ks = 0; ks < 64; ks += 8) {
            unsigned a[2][4], bb[4][2];
#pragma unroll
            for (int mi = 0; mi < 2; mi++) {
                const unsigned* p = &Ps[(wm + mi * 16 + lr) * 72 + ks + lc];
                a[mi][0] = p[0]; a[mi][1] = p[576]; a[mi][2] = p[4]; a[mi][3] = p[580];
            }
#pragma unroll
            for (int ni = 0; ni < 4; ni++) {
                const unsigned* p = &Vs[(ks + lc) * 72 + wn + ni * 8 + lr];
                bb[ni][0] = p[0]; bb[ni][1] = p[288];
            }
#pragma unroll
            for (int mi = 0; mi < 2; mi++)
#pragma unroll
                for (int ni = 0; ni < 4; ni++)
                    mma8(oacc[mi][ni], a[mi], bb[ni]);
        }
        __syncthreads();
    }

    // finalize
    float* Og = g_o + base + (size_t)qt * 128 * 64;
#pragma unroll
    for (int mi = 0; mi < 2; mi++) {
        int r = wm + mi * 16 + lr;
        float li0 = 1.f / l_s[r];
        float li1 = 1.f / l_s[r + 8];
#pragma unroll
        for (int ni = 0; ni < 4; ni++) {
            int c = wn + ni * 8 + 2 * lc;
            *reinterpret_cast<float2*>(Og + r * 64 + c) =
                make_float2(oacc[mi][ni][0] * li0, oacc[mi][ni][1] * li0);
            *reinterpret_cast<float2*>(Og + (r + 8) * 64 + c) =
                make_float2(oacc[mi][ni][2] * li1, oacc[mi][ni][3] * li1);
        }
    }
}

// ---------------------------------------------------------------------------
// Kernel 3: proj GEMM. out[b,o,token] = sum_v pw[o,v]*O[b,h(v),token,d(v)]
// Block 128m(token) x 128n(o), BK=16, K=512. Double-buffered.
// As [m][k] ld40 (row-major A), Bs [n][k] ld40. Transpose epilogue.
// ---------------------------------------------------------------------------
__global__ void proj_gemm_kernel(const float* __restrict__ pw,
                                 const float* __restrict__ pb,
                                 float* __restrict__ out)
{
    extern __shared__ unsigned smem[];
    unsigned* As = smem;            // [2][128][40]
    unsigned* Bs = smem + 10240;    // [2][128][40]

    const int b  = blockIdx.z;
    const int mT = blockIdx.x * 128;
    const int nT = blockIdx.y * 128;
    const int t = threadIdx.x;
    const int lane = t & 31;
    const int warp = t >> 5;
    const int wm = (warp & 1) * 64;
    const int wn = (warp >> 1) * 32;
    const int lr = lane >> 2;
    const int lc = lane & 3;

    float acc[4][4][4];
#pragma unroll
    for (int i = 0; i < 4; i++)
#pragma unroll
        for (int j = 0; j < 4; j++)
#pragma unroll
            for (int q = 0; q < 4; q++) acc[i][j][q] = 0.f;

    const int a_tok = t >> 2, a_kd = (t & 3) * 4;
    const int b_n   = t >> 2, b_k  = (t & 3) * 4;

    float4 ax[2], bx[2];
    const float* ob = g_o + (size_t)b * (NHEAD * NTOK * 64);

#pragma unroll
    for (int i = 0; i < 2; i++)
        ax[i] = *reinterpret_cast<const float4*>(
            ob + (size_t)(mT + a_tok + i * 64) * 64 + a_kd);   // kk=0: head 0, d0 0
#pragma unroll
    for (int i = 0; i < 2; i++)
        bx[i] = *reinterpret_cast<const float4*>(pw + (size_t)(nT + b_n + i * 64) * 512 + b_k);
    {
#pragma unroll
        for (int i = 0; i < 2; i++)
            *reinterpret_cast<uint4*>(&As[(a_tok + i * 64) * 40 + a_kd]) = f2tf4(ax[i]);
#pragma unroll
        for (int i = 0; i < 2; i++)
            *reinterpret_cast<uint4*>(&Bs[(b_n + i * 64) * 40 + b_k]) = f2tf4(bx[i]);
    }
    __syncthreads();

    for (int it = 0; it < 32; it++) {
        const unsigned* Ac = As + (it & 1) * 5120;
        const unsigned* Bc = Bs + (it & 1) * 5120;
        if (it < 31) {
            int kk = (it + 1) * 16;
            int head = kk >> 6, d0 = kk & 63;
            const float* oh = ob + (size_t)head * (NTOK * 64);
#pragma unroll
            for (int i = 0; i < 2; i++)
                ax[i] = *reinterpret_cast<const float4*>(
                    oh + (size_t)(mT + a_tok + i * 64) * 64 + d0 + a_kd);
#pragma unroll
            for (int i = 0; i < 2; i++)
                bx[i] = *reinterpret_cast<const float4*>(pw + (size_t)(nT + b_n + i * 64) * 512 + kk + b_k);
        }
#pragma unroll
        for (int ks = 0; ks < 16; ks += 8) {
            unsigned a[4][4], bb[4][2];
#pragma unroll
            for (int mi = 0; mi < 4; mi++) {
                const unsigned* p = &Ac[(wm + mi * 16 + lr) * 40 + ks + lc];
                a[mi][0] = p[0]; a[mi][1] = p[320]; a[mi][2] = p[4]; a[mi][3] = p[324];
            }
#pragma unroll
            for (int ni = 0; ni < 4; ni++) {
                const unsigned* p = &Bc[(wn + ni * 8 + lr) * 40 + ks + lc];
                bb[ni][0] = p[0]; bb[ni][1] = p[4];
            }
#pragma unroll
            for (int mi = 0; mi < 4; mi++)
#pragma unroll
                for (int ni = 0; ni < 4; ni++)
                    mma8(acc[mi][ni], a[mi], bb[ni]);
        }
        if (it < 31) {
            unsigned* Ab = As + ((it + 1) & 1) * 5120;
            unsigned* Bb = Bs + ((it + 1) & 1) * 5120;
#pragma unroll
            for (int i = 0; i < 2; i++)
                *reinterpret_cast<uint4*>(&Ab[(a_tok + i * 64) * 40 + a_kd]) = f2tf4(ax[i]);
#pragma unroll
            for (int i = 0; i < 2; i++)
                *reinterpret_cast<uint4*>(&Bb[(b_n + i * 64) * 40 + b_k]) = f2tf4(bx[i]);
        }
        __syncthreads();
    }

    // transpose epilogue through smem: Cs[n][m] ld132
    float* Cs = (float*)smem;
#pragma unroll
    for (int ni = 0; ni < 4; ni++) {
        int n = wn + ni * 8 + 2 * lc;
#pragma unroll
        for (int mi = 0; mi < 4; mi++) {
            int m = wm + mi * 16 + lr;
            Cs[n * 132 + m]           = acc[mi][ni][0];
            Cs[(n + 1) * 132 + m]     = acc[mi][ni][1];
            Cs[n * 132 + m + 8]       = acc[mi][ni][2];
            Cs[(n + 1) * 132 + m + 8] = acc[mi][ni][3];
        }
    }
    __syncthreads();

#pragma unroll
    for (int i = 0; i < 16; i++) {
        int idx = t + i * 256;
        int n = idx >> 5, mq = (idx & 31) * 4;
        float bi = pb[nT + n];
        const float* src = &Cs[n * 132 + mq];
        float4 v;
        v.x = src[0] + bi; v.y = src[1] + bi; v.z = src[2] + bi; v.w = src[3] + bi;
        *reinterpret_cast<float4*>(out + (size_t)(b * 256 + nT + n) * NTOK + mT + mq) = v;
    }
}

// ---------------------------------------------------------------------------
extern "C" void kernel_launch(void* const* d_in, const int* in_sizes, int n_in,
                              void* d_out, int out_size)
{
    const float* x      = (const float*)d_in[0];
    const float* qkv_w  = (const float*)d_in[1];
    const float* qkv_b  = (const float*)d_in[2];
    const float* proj_w = (const float*)d_in[3];
    const float* proj_b = (const float*)d_in[4];
    float* out = (float*)d_out;

    const int qkv_smem  = (4352 + 10240) * 4;          // 58368
    const int attn_smem = 28032 * 4;                   // 112128
    const int proj_smem = 20480 * 4;                   // 81920
    cudaFuncSetAttribute(qkv_gemm_kernel, cudaFuncAttributeMaxDynamicSharedMemorySize, qkv_smem);
    cudaFuncSetAttribute(attn_kernel, cudaFuncAttributeMaxDynamicSharedMemorySize, attn_smem);
    cudaFuncSetAttribute(proj_gemm_kernel, cudaFuncAttributeMaxDynamicSharedMemorySize, proj_smem);

    qkv_gemm_kernel<<<dim3(8, 12, BATCH), 256, qkv_smem>>>(x, qkv_w, qkv_b);
    attn_kernel<<<dim3(8, NHEAD, BATCH), 256, attn_smem>>>();
    proj_gemm_kernel<<<dim3(8, 2, BATCH), 256, proj_smem>>>(proj_w, proj_b, out);
}

// round 5
// speedup vs baseline: 2.8176x; 1.0681x over previous
#include <cuda_runtime.h>
#include <cuda_bf16.h>

#define BATCH   16
#define IN_CH   256
#define NTOK    1024
#define NHEAD   8
// SCALE * log2(e): softmax done in exp2 domain
#define QSCALE  0.18033688f

// Scratch: [B, H, N, D]
__device__ __align__(16) float g_q[BATCH * NHEAD * NTOK * 64];
__device__ __align__(16) float g_k[BATCH * NHEAD * NTOK * 64];
__device__ __align__(16) float g_v[BATCH * NHEAD * NTOK * 64];
__device__ __align__(16) float g_o[BATCH * NHEAD * NTOK * 64];

__device__ __forceinline__ unsigned f2tf(float f) {
    unsigned u;
    asm("cvt.rna.tf32.f32 %0, %1;" : "=r"(u) : "f"(f));
    return u;
}

__device__ __forceinline__ void mma8(float* d, const unsigned* a, const unsigned* b) {
    asm volatile(
        "mma.sync.aligned.m16n8k8.row.col.f32.tf32.tf32.f32 "
        "{%0,%1,%2,%3}, {%4,%5,%6,%7}, {%8,%9}, {%0,%1,%2,%3};\n"
        : "+f"(d[0]), "+f"(d[1]), "+f"(d[2]), "+f"(d[3])
        : "r"(a[0]), "r"(a[1]), "r"(a[2]), "r"(a[3]), "r"(b[0]), "r"(b[1]));
}

__device__ __forceinline__ uint4 f2tf4(float4 v) {
    uint4 u;
    u.x = f2tf(v.x); u.y = f2tf(v.y); u.z = f2tf(v.z); u.w = f2tf(v.w);
    return u;
}

__device__ __forceinline__ float ex2(float x) {
    float r;
    asm("ex2.approx.f32 %0, %1;" : "=f"(r) : "f"(x));
    return r;
}

// ---------------------------------------------------------------------------
// Kernel 1: QKV GEMM (HMMA tf32, double-buffered; round-3 proven version)
// ---------------------------------------------------------------------------
__global__ void qkv_gemm_kernel(const float* __restrict__ x,
                                const float* __restrict__ w,
                                const float* __restrict__ bias)
{
    extern __shared__ unsigned smem[];
    unsigned* As = smem;            // [2][16][136]
    unsigned* Bs = smem + 4352;     // [2][128][40]

    const int b  = blockIdx.z;
    const int mT = blockIdx.x * 128;
    const int nT = blockIdx.y * 128;
    const int t = threadIdx.x;
    const int lane = t & 31;
    const int warp = t >> 5;
    const int wm = (warp & 1) * 64;
    const int wn = (warp >> 1) * 32;
    const int lr = lane >> 2;
    const int lc = lane & 3;

    const float* xb = x + (size_t)b * (IN_CH * NTOK);

    float acc[4][4][4];
#pragma unroll
    for (int i = 0; i < 4; i++)
#pragma unroll
        for (int j = 0; j < 4; j++)
#pragma unroll
            for (int q = 0; q < 4; q++) acc[i][j][q] = 0.f;

    const int a_m = (t & 31) * 4, a_k = t >> 5;
    const int b_n = t >> 2,       b_k = (t & 3) * 4;

    float4 ax[2], bx[2];
#pragma unroll
    for (int i = 0; i < 2; i++)
        ax[i] = *reinterpret_cast<const float4*>(xb + (size_t)(a_k + i * 8) * NTOK + mT + a_m);
#pragma unroll
    for (int i = 0; i < 2; i++)
        bx[i] = *reinterpret_cast<const float4*>(w + (size_t)(nT + b_n + i * 64) * IN_CH + b_k);
    {
#pragma unroll
        for (int i = 0; i < 2; i++)
            *reinterpret_cast<uint4*>(&As[(a_k + i * 8) * 136 + a_m]) = f2tf4(ax[i]);
#pragma unroll
        for (int i = 0; i < 2; i++)
            *reinterpret_cast<uint4*>(&Bs[(b_n + i * 64) * 40 + b_k]) = f2tf4(bx[i]);
    }
    __syncthreads();

    for (int it = 0; it < 16; it++) {
        const unsigned* Ac = As + (it & 1) * 2176;
        const unsigned* Bc = Bs + (it & 1) * 5120;
        if (it < 15) {
            int kk = (it + 1) * 16;
#pragma unroll
            for (int i = 0; i < 2; i++)
                ax[i] = *reinterpret_cast<const float4*>(xb + (size_t)(kk + a_k + i * 8) * NTOK + mT + a_m);
#pragma unroll
            for (int i = 0; i < 2; i++)
                bx[i] = *reinterpret_cast<const float4*>(w + (size_t)(nT + b_n + i * 64) * IN_CH + kk + b_k);
        }
#pragma unroll
        for (int ks = 0; ks < 16; ks += 8) {
            unsigned a[4][4], bb[4][2];
#pragma unroll
            for (int mi = 0; mi < 4; mi++) {
                const unsigned* p = &Ac[(ks + lc) * 136 + wm + mi * 16 + lr];
                a[mi][0] = p[0]; a[mi][1] = p[8]; a[mi][2] = p[544]; a[mi][3] = p[552];
            }
#pragma unroll
            for (int ni = 0; ni < 4; ni++) {
                const unsigned* p = &Bc[(wn + ni * 8 + lr) * 40 + ks + lc];
                bb[ni][0] = p[0]; bb[ni][1] = p[4];
            }
#pragma unroll
            for (int mi = 0; mi < 4; mi++)
#pragma unroll
                for (int ni = 0; ni < 4; ni++)
                    mma8(acc[mi][ni], a[mi], bb[ni]);
        }
        if (it < 15) {
            unsigned* Ab = As + ((it + 1) & 1) * 2176;
            unsigned* Bb = Bs + ((it + 1) & 1) * 5120;
#pragma unroll
            for (int i = 0; i < 2; i++)
                *reinterpret_cast<uint4*>(&Ab[(a_k + i * 8) * 136 + a_m]) = f2tf4(ax[i]);
#pragma unroll
            for (int i = 0; i < 2; i++)
                *reinterpret_cast<uint4*>(&Bb[(b_n + i * 64) * 40 + b_k]) = f2tf4(bx[i]);
        }
        __syncthreads();
    }

    // epilogue: scatter to g_q/g_k/g_v [b,h,token,d]; q pre-scaled by SCALE*log2e
#pragma unroll
    for (int ni = 0; ni < 4; ni++) {
        int o = nT + wn + ni * 8 + 2 * lc;
        float* dst;
        float sc = 1.f;
        if (o < 512)       { dst = g_q; sc = QSCALE; }
        else if (o < 1024) { dst = g_k; }
        else               { dst = g_v; }
        int head = (o >> 6) & 7;
        int d = o & 63;
        float b0 = bias[o], b1 = bias[o + 1];
        float* base = dst + ((size_t)(b * NHEAD + head) * NTOK) * 64 + d;
#pragma unroll
        for (int mi = 0; mi < 4; mi++) {
            int r = mT + wm + mi * 16 + lr;
            *reinterpret_cast<float2*>(base + (size_t)r * 64) =
                make_float2((acc[mi][ni][0] + b0) * sc, (acc[mi][ni][1] + b1) * sc);
            *reinterpret_cast<float2*>(base + (size_t)(r + 8) * 64) =
                make_float2((acc[mi][ni][2] + b0) * sc, (acc[mi][ni][3] + b1) * sc);
        }
    }
}

// ---------------------------------------------------------------------------
// Kernel 2: causal flash attention. BM=128, BN=128, 256 threads.
// S phase: 8 warps 2m x 4n, warp tile 64x32 (1.5 LDS/mma).
// PV phase: 8 warps 4m x 2n, warp tile 32x32 (dv=64).
// Softmax in exp2 domain (q pre-scaled by log2e), raw EX2.
// ---------------------------------------------------------------------------
__global__ void __launch_bounds__(256, 1) attn_kernel()
{
    extern __shared__ unsigned sm[];
    unsigned* Qs = sm;               // [128][72] tf32
    unsigned* Ks = sm + 9216;        // [128][72] tf32
    unsigned* Vs = sm + 18432;       // [128][72] tf32
    unsigned* Ps = sm + 27648;       // [128][136]  S(float) then P(tf32)
    float* Sf  = (float*)Ps;
    float* m_s = (float*)(sm + 45056);
    float* l_s = m_s + 128;
    float* a_s = l_s + 128;

    const int t = threadIdx.x, lane = t & 31, warp = t >> 5;
    // S-phase warp map (2m x 4n)
    const int wm = (warp & 1) * 64;
    const int wn = (warp >> 1) * 32;
    // PV-phase warp map (4m x 2n)
    const int pm = (warp & 3) * 32;
    const int pn = (warp >> 2) * 32;
    const int lr = lane >> 2, lc = lane & 3;
    const int qt = 7 - blockIdx.x;   // heavy blocks first
    const int h = blockIdx.y, b = blockIdx.z;

    const size_t base = (size_t)(b * NHEAD + h) * (NTOK * 64);
    const float* Qg = g_q + base + (size_t)qt * 128 * 64;
    const float* Kg = g_k + base;
    const float* Vg = g_v + base;

    const int lrow = t >> 4, lcol = (t & 15) * 4;
#pragma unroll
    for (int i = 0; i < 8; i++) {
        int r = lrow + i * 16;
        float4 v = *reinterpret_cast<const float4*>(Qg + r * 64 + lcol);
        *reinterpret_cast<uint4*>(&Qs[r * 72 + lcol]) = f2tf4(v);
    }
    if (t < 128) { m_s[t] = -1e30f; l_s[t] = 0.f; }

    float oacc[2][4][4];
#pragma unroll
    for (int i = 0; i < 2; i++)
#pragma unroll
        for (int j = 0; j < 4; j++)
#pragma unroll
            for (int q = 0; q < 4; q++) oacc[i][j][q] = 0.f;

    const int sr = t >> 1, sq = t & 1;

    float4 kreg[8], vreg[8];
#pragma unroll
    for (int i = 0; i < 8; i++) {
        int r = lrow + i * 16;
        kreg[i] = *reinterpret_cast<const float4*>(Kg + r * 64 + lcol);
        vreg[i] = *reinterpret_cast<const float4*>(Vg + r * 64 + lcol);
    }
    __syncthreads();

    for (int kt = 0; kt <= qt; kt++) {
        // stage current K/V tile into smem
#pragma unroll
        for (int i = 0; i < 8; i++) {
            int r = lrow + i * 16;
            *reinterpret_cast<uint4*>(&Ks[r * 72 + lcol]) = f2tf4(kreg[i]);
            *reinterpret_cast<uint4*>(&Vs[r * 72 + lcol]) = f2tf4(vreg[i]);
        }
        __syncthreads();

        // ---- S = Q K^T (warp tile 64x32) ----
        float s[4][4][4];
#pragma unroll
        for (int i = 0; i < 4; i++)
#pragma unroll
            for (int j = 0; j < 4; j++)
#pragma unroll
                for (int q = 0; q < 4; q++) s[i][j][q] = 0.f;
#pragma unroll
        for (int ks = 0; ks < 64; ks += 8) {
            unsigned a[4][4], bb[4][2];
#pragma unroll
            for (int mi = 0; mi < 4; mi++) {
                const unsigned* p = &Qs[(wm + mi * 16 + lr) * 72 + ks + lc];
                a[mi][0] = p[0]; a[mi][1] = p[576]; a[mi][2] = p[4]; a[mi][3] = p[580];
            }
#pragma unroll
            for (int ni = 0; ni < 4; ni++) {
                const unsigned* p = &Ks[(wn + ni * 8 + lr) * 72 + ks + lc];
                bb[ni][0] = p[0]; bb[ni][1] = p[4];
            }
#pragma unroll
            for (int mi = 0; mi < 4; mi++)
#pragma unroll
                for (int ni = 0; ni < 4; ni++)
                    mma8(s[mi][ni], a[mi], bb[ni]);
        }
        const bool partial = (kt == qt);
#pragma unroll
        for (int mi = 0; mi < 4; mi++)
#pragma unroll
            for (int ni = 0; ni < 4; ni++) {
                int r = wm + mi * 16 + lr;
                int c = wn + ni * 8 + 2 * lc;
                float v0 = s[mi][ni][0], v1 = s[mi][ni][1];
                float v2 = s[mi][ni][2], v3 = s[mi][ni][3];
                if (partial) {
                    if (c > r)         v0 = -1e30f;
                    if (c + 1 > r)     v1 = -1e30f;
                    if (c > r + 8)     v2 = -1e30f;
                    if (c + 1 > r + 8) v3 = -1e30f;
                }
                *reinterpret_cast<float2*>(&Sf[r * 136 + c]) = make_float2(v0, v1);
                *reinterpret_cast<float2*>(&Sf[(r + 8) * 136 + c]) = make_float2(v2, v3);
            }
        __syncthreads();

        // ---- online softmax (2 threads/row, exp2 domain) ----
        {
            const float4* rp = reinterpret_cast<const float4*>(&Sf[sr * 136 + sq * 64]);
            float4 v[16];
            float mloc = -1e30f;
#pragma unroll
            for (int j = 0; j < 16; j++) {
                v[j] = rp[j];
                mloc = fmaxf(mloc, fmaxf(fmaxf(v[j].x, v[j].y), fmaxf(v[j].z, v[j].w)));
            }
            mloc = fmaxf(mloc, __shfl_xor_sync(0xffffffffu, mloc, 1));
            float mprev = m_s[sr];
            float mnew  = fmaxf(mprev, mloc);
            float ssum = 0.f;
            uint4* wp = reinterpret_cast<uint4*>(&Ps[sr * 136 + sq * 64]);
#pragma unroll
            for (int j = 0; j < 16; j++) {
                float e0 = ex2(v[j].x - mnew);
                float e1 = ex2(v[j].y - mnew);
                float e2 = ex2(v[j].z - mnew);
                float e3 = ex2(v[j].w - mnew);
                ssum += (e0 + e1) + (e2 + e3);
                uint4 u;
                u.x = f2tf(e0); u.y = f2tf(e1); u.z = f2tf(e2); u.w = f2tf(e3);
                wp[j] = u;
            }
            ssum += __shfl_xor_sync(0xffffffffu, ssum, 1);
            if (sq == 0) {
                float alpha = ex2(mprev - mnew);
                m_s[sr] = mnew;
                l_s[sr] = l_s[sr] * alpha + ssum;
                a_s[sr] = alpha;
            }
        }
        __syncthreads();

        // prefetch next K/V tile (s[] is dead now -> low reg pressure)
        if (kt < qt) {
            const float* kg = Kg + (size_t)(kt + 1) * 128 * 64;
            const float* vg = Vg + (size_t)(kt + 1) * 128 * 64;
#pragma unroll
            for (int i = 0; i < 8; i++) {
                int r = lrow + i * 16;
                kreg[i] = *reinterpret_cast<const float4*>(kg + r * 64 + lcol);
                vreg[i] = *reinterpret_cast<const float4*>(vg + r * 64 + lcol);
            }
        }

        // ---- O = O*alpha + P V (warp tile 32x32, k=128) ----
#pragma unroll
        for (int mi = 0; mi < 2; mi++) {
            float al0 = a_s[pm + mi * 16 + lr];
            float al1 = a_s[pm + mi * 16 + lr + 8];
#pragma unroll
            for (int ni = 0; ni < 4; ni++) {
                oacc[mi][ni][0] *= al0; oacc[mi][ni][1] *= al0;
                oacc[mi][ni][2] *= al1; oacc[mi][ni][3] *= al1;
            }
        }
#pragma unroll
        for (int ks = 0; ks < 128; ks += 8) {
            unsigned a[2][4], bb[4][2];
#pragma unroll
            for (int mi = 0; mi < 2; mi++) {
                const unsigned* p = &Ps[(pm + mi * 16 + lr) * 136 + ks + lc];
                a[mi][0] = p[0]; a[mi][1] = p[1088]; a[mi][2] = p[4]; a[mi][3] = p[1092];
            }
#pragma unroll
            for (int ni = 0; ni < 4; ni++) {
                const unsigned* p = &Vs[(ks + lc) * 72 + pn + ni * 8 + lr];
                bb[ni][0] = p[0]; bb[ni][1] = p[288];
            }
#pragma unroll
            for (int mi = 0; mi < 2; mi++)
#pragma unroll
                for (int ni = 0; ni < 4; ni++)
                    mma8(oacc[mi][ni], a[mi], bb[ni]);
        }
        __syncthreads();
    }

    // finalize: O /= l, write [b,h,token,d]
    float* Og = g_o + base + (size_t)qt * 128 * 64;
#pragma unroll
    for (int mi = 0; mi < 2; mi++) {
        int r = pm + mi * 16 + lr;
        float li0 = 1.f / l_s[r];
        float li1 = 1.f / l_s[r + 8];
#pragma unroll
        for (int ni = 0; ni < 4; ni++) {
            int c = pn + ni * 8 + 2 * lc;
            *reinterpret_cast<float2*>(Og + r * 64 + c) =
                make_float2(oacc[mi][ni][0] * li0, oacc[mi][ni][1] * li0);
            *reinterpret_cast<float2*>(Og + (r + 8) * 64 + c) =
                make_float2(oacc[mi][ni][2] * li1, oacc[mi][ni][3] * li1);
        }
    }
}

// ---------------------------------------------------------------------------
// Kernel 3: proj GEMM (HMMA tf32, double-buffered; round-3 proven version)
// ---------------------------------------------------------------------------
__global__ void proj_gemm_kernel(const float* __restrict__ pw,
                                 const float* __restrict__ pb,
                                 float* __restrict__ out)
{
    extern __shared__ unsigned smem[];
    unsigned* As = smem;            // [2][128][40]
    unsigned* Bs = smem + 10240;    // [2][128][40]

    const int b  = blockIdx.z;
    const int mT = blockIdx.x * 128;
    const int nT = blockIdx.y * 128;
    const int t = threadIdx.x;
    const int lane = t & 31;
    const int warp = t >> 5;
    const int wm = (warp & 1) * 64;
    const int wn = (warp >> 1) * 32;
    const int lr = lane >> 2;
    const int lc = lane & 3;

    float acc[4][4][4];
#pragma unroll
    for (int i = 0; i < 4; i++)
#pragma unroll
        for (int j = 0; j < 4; j++)
#pragma unroll
            for (int q = 0; q < 4; q++) acc[i][j][q] = 0.f;

    const int a_tok = t >> 2, a_kd = (t & 3) * 4;
    const int b_n   = t >> 2, b_k  = (t & 3) * 4;

    float4 ax[2], bx[2];
    const float* ob = g_o + (size_t)b * (NHEAD * NTOK * 64);

#pragma unroll
    for (int i = 0; i < 2; i++)
        ax[i] = *reinterpret_cast<const float4*>(
            ob + (size_t)(mT + a_tok + i * 64) * 64 + a_kd);
#pragma unroll
    for (int i = 0; i < 2; i++)
        bx[i] = *reinterpret_cast<const float4*>(pw + (size_t)(nT + b_n + i * 64) * 512 + b_k);
    {
#pragma unroll
        for (int i = 0; i < 2; i++)
            *reinterpret_cast<uint4*>(&As[(a_tok + i * 64) * 40 + a_kd]) = f2tf4(ax[i]);
#pragma unroll
        for (int i = 0; i < 2; i++)
            *reinterpret_cast<uint4*>(&Bs[(b_n + i * 64) * 40 + b_k]) = f2tf4(bx[i]);
    }
    __syncthreads();

    for (int it = 0; it < 32; it++) {
        const unsigned* Ac = As + (it & 1) * 5120;
        const unsigned* Bc = Bs + (it & 1) * 5120;
        if (it < 31) {
            int kk = (it + 1) * 16;
            int head = kk >> 6, d0 = kk & 63;
            const float* oh = ob + (size_t)head * (NTOK * 64);
#pragma unroll
            for (int i = 0; i < 2; i++)
                ax[i] = *reinterpret_cast<const float4*>(
                    oh + (size_t)(mT + a_tok + i * 64) * 64 + d0 + a_kd);
#pragma unroll
            for (int i = 0; i < 2; i++)
                bx[i] = *reinterpret_cast<const float4*>(pw + (size_t)(nT + b_n + i * 64) * 512 + kk + b_k);
        }
#pragma unroll
        for (int ks = 0; ks < 16; ks += 8) {
            unsigned a[4][4], bb[4][2];
#pragma unroll
            for (int mi = 0; mi < 4; mi++) {
                const unsigned* p = &Ac[(wm + mi * 16 + lr) * 40 + ks + lc];
                a[mi][0] = p[0]; a[mi][1] = p[320]; a[mi][2] = p[4]; a[mi][3] = p[324];
            }
#pragma unroll
            for (int ni = 0; ni < 4; ni++) {
                const unsigned* p = &Bc[(wn + ni * 8 + lr) * 40 + ks + lc];
                bb[ni][0] = p[0]; bb[ni][1] = p[4];
            }
#pragma unroll
            for (int mi = 0; mi < 4; mi++)
#pragma unroll
                for (int ni = 0; ni < 4; ni++)
                    mma8(acc[mi][ni], a[mi], bb[ni]);
        }
        if (it < 31) {
            unsigned* Ab = As + ((it + 1) & 1) * 5120;
            unsigned* Bb = Bs + ((it + 1) & 1) * 5120;
#pragma unroll
            for (int i = 0; i < 2; i++)
                *reinterpret_cast<uint4*>(&Ab[(a_tok + i * 64) * 40 + a_kd]) = f2tf4(ax[i]);
#pragma unroll
            for (int i = 0; i < 2; i++)
                *reinterpret_cast<uint4*>(&Bb[(b_n + i * 64) * 40 + b_k]) = f2tf4(bx[i]);
        }
        __syncthreads();
    }

    // transpose epilogue through smem: Cs[n][m] ld132
    float* Cs = (float*)smem;
#pragma unroll
    for (int ni = 0; ni < 4; ni++) {
        int n = wn + ni * 8 + 2 * lc;
#pragma unroll
        for (int mi = 0; mi < 4; mi++) {
            int m = wm + mi * 16 + lr;
            Cs[n * 132 + m]           = acc[mi][ni][0];
            Cs[(n + 1) * 132 + m]     = acc[mi][ni][1];
            Cs[n * 132 + m + 8]       = acc[mi][ni][2];
            Cs[(n + 1) * 132 + m + 8] = acc[mi][ni][3];
        }
    }
    __syncthreads();

#pragma unroll
    for (int i = 0; i < 16; i++) {
        int idx = t + i * 256;
        int n = idx >> 5, mq = (idx & 31) * 4;
        float bi = pb[nT + n];
        const float* src = &Cs[n * 132 + mq];
        float4 v;
        v.x = src[0] + bi; v.y = src[1] + bi; v.z = src[2] + bi; v.w = src[3] + bi;
        *reinterpret_cast<float4*>(out + (size_t)(b * 256 + nT + n) * NTOK + mT + mq) = v;
    }
}

// ---------------------------------------------------------------------------
extern "C" void kernel_launch(void* const* d_in, const int* in_sizes, int n_in,
                              void* d_out, int out_size)
{
    const float* x      = (const float*)d_in[0];
    const float* qkv_w  = (const float*)d_in[1];
    const float* qkv_b  = (const float*)d_in[2];
    const float* proj_w = (const float*)d_in[3];
    const float* proj_b = (const float*)d_in[4];
    float* out = (float*)d_out;

    const int qkv_smem  = (4352 + 10240) * 4;          // 58368
    const int attn_smem = 45440 * 4;                   // 181760
    const int proj_smem = 20480 * 4;                   // 81920
    cudaFuncSetAttribute(qkv_gemm_kernel, cudaFuncAttributeMaxDynamicSharedMemorySize, qkv_smem);
    cudaFuncSetAttribute(attn_kernel, cudaFuncAttributeMaxDynamicSharedMemorySize, attn_smem);
    cudaFuncSetAttribute(proj_gemm_kernel, cudaFuncAttributeMaxDynamicSharedMemorySize, proj_smem);

    qkv_gemm_kernel<<<dim3(8, 12, BATCH), 256, qkv_smem>>>(x, qkv_w, qkv_b);
    attn_kernel<<<dim3(8, NHEAD, BATCH), 256, attn_smem>>>();
    proj_gemm_kernel<<<dim3(8, 2, BATCH), 256, proj_smem>>>(proj_w, proj_b, out);
}

// round 6
// speedup vs baseline: 3.1605x; 1.1217x over previous
#include <cuda_runtime.h>
#include <cuda_bf16.h>

#define BATCH   16
#define IN_CH   256
#define NTOK    1024
#define NHEAD   8
// SCALE * log2(e): softmax done in exp2 domain
#define QSCALE  0.18033688f

// Scratch: [B, H, N, D]
__device__ __align__(16) float g_q[BATCH * NHEAD * NTOK * 64];
__device__ __align__(16) float g_k[BATCH * NHEAD * NTOK * 64];
__device__ __align__(16) float g_v[BATCH * NHEAD * NTOK * 64];
__device__ __align__(16) float g_o[BATCH * NHEAD * NTOK * 64];

__device__ __forceinline__ unsigned f2tf(float f) {
    unsigned u;
    asm("cvt.rna.tf32.f32 %0, %1;" : "=r"(u) : "f"(f));
    return u;
}

__device__ __forceinline__ void mma8(float* d, const unsigned* a, const unsigned* b) {
    asm volatile(
        "mma.sync.aligned.m16n8k8.row.col.f32.tf32.tf32.f32 "
        "{%0,%1,%2,%3}, {%4,%5,%6,%7}, {%8,%9}, {%0,%1,%2,%3};\n"
        : "+f"(d[0]), "+f"(d[1]), "+f"(d[2]), "+f"(d[3])
        : "r"(a[0]), "r"(a[1]), "r"(a[2]), "r"(a[3]), "r"(b[0]), "r"(b[1]));
}

__device__ __forceinline__ uint4 f2tf4(float4 v) {
    uint4 u;
    u.x = f2tf(v.x); u.y = f2tf(v.y); u.z = f2tf(v.z); u.w = f2tf(v.w);
    return u;
}

__device__ __forceinline__ float ex2(float x) {
    float r;
    asm("ex2.approx.f32 %0, %1;" : "=f"(r) : "f"(x));
    return r;
}

// ---------------------------------------------------------------------------
// Kernel 1: QKV GEMM. Block 128m x 256n, BK=16, 8 warps (2m x 4n), warp 64x64.
// Double-buffered. As [k][m] ld136, Bs [n][k] ld40.
// ---------------------------------------------------------------------------
__global__ void qkv_gemm_kernel(const float* __restrict__ x,
                                const float* __restrict__ w,
                                const float* __restrict__ bias)
{
    extern __shared__ unsigned smem[];
    unsigned* As = smem;            // [2][16][136]  = 4352
    unsigned* Bs = smem + 4352;     // [2][256][40]  = 20480

    const int b  = blockIdx.z;
    const int mT = blockIdx.x * 128;
    const int nT = blockIdx.y * 256;
    const int t = threadIdx.x;
    const int lane = t & 31;
    const int warp = t >> 5;
    const int wm = (warp & 1) * 64;
    const int wn = (warp >> 1) * 64;
    const int lr = lane >> 2;
    const int lc = lane & 3;

    const float* xb = x + (size_t)b * (IN_CH * NTOK);

    float acc[4][8][4];
#pragma unroll
    for (int i = 0; i < 4; i++)
#pragma unroll
        for (int j = 0; j < 8; j++)
#pragma unroll
            for (int q = 0; q < 4; q++) acc[i][j][q] = 0.f;

    const int a_m = (t & 31) * 4, a_k = t >> 5;
    const int b_n = t >> 2,       b_k = (t & 3) * 4;

    float4 ax[2], bx[4];
#pragma unroll
    for (int i = 0; i < 2; i++)
        ax[i] = *reinterpret_cast<const float4*>(xb + (size_t)(a_k + i * 8) * NTOK + mT + a_m);
#pragma unroll
    for (int i = 0; i < 4; i++)
        bx[i] = *reinterpret_cast<const float4*>(w + (size_t)(nT + b_n + i * 64) * IN_CH + b_k);
    {
#pragma unroll
        for (int i = 0; i < 2; i++)
            *reinterpret_cast<uint4*>(&As[(a_k + i * 8) * 136 + a_m]) = f2tf4(ax[i]);
#pragma unroll
        for (int i = 0; i < 4; i++)
            *reinterpret_cast<uint4*>(&Bs[(b_n + i * 64) * 40 + b_k]) = f2tf4(bx[i]);
    }
    __syncthreads();

    for (int it = 0; it < 16; it++) {
        const unsigned* Ac = As + (it & 1) * 2176;
        const unsigned* Bc = Bs + (it & 1) * 10240;
        if (it < 15) {
            int kk = (it + 1) * 16;
#pragma unroll
            for (int i = 0; i < 2; i++)
                ax[i] = *reinterpret_cast<const float4*>(xb + (size_t)(kk + a_k + i * 8) * NTOK + mT + a_m);
#pragma unroll
            for (int i = 0; i < 4; i++)
                bx[i] = *reinterpret_cast<const float4*>(w + (size_t)(nT + b_n + i * 64) * IN_CH + kk + b_k);
        }
#pragma unroll
        for (int ks = 0; ks < 16; ks += 8) {
            unsigned a[4][4], bb[8][2];
#pragma unroll
            for (int mi = 0; mi < 4; mi++) {
                const unsigned* p = &Ac[(ks + lc) * 136 + wm + mi * 16 + lr];
                a[mi][0] = p[0]; a[mi][1] = p[8]; a[mi][2] = p[544]; a[mi][3] = p[552];
            }
#pragma unroll
            for (int ni = 0; ni < 8; ni++) {
                const unsigned* p = &Bc[(wn + ni * 8 + lr) * 40 + ks + lc];
                bb[ni][0] = p[0]; bb[ni][1] = p[4];
            }
#pragma unroll
            for (int mi = 0; mi < 4; mi++)
#pragma unroll
                for (int ni = 0; ni < 8; ni++)
                    mma8(acc[mi][ni], a[mi], bb[ni]);
        }
        if (it < 15) {
            unsigned* Ab = As + ((it + 1) & 1) * 2176;
            unsigned* Bb = Bs + ((it + 1) & 1) * 10240;
#pragma unroll
            for (int i = 0; i < 2; i++)
                *reinterpret_cast<uint4*>(&Ab[(a_k + i * 8) * 136 + a_m]) = f2tf4(ax[i]);
#pragma unroll
            for (int i = 0; i < 4; i++)
                *reinterpret_cast<uint4*>(&Bb[(b_n + i * 64) * 40 + b_k]) = f2tf4(bx[i]);
        }
        __syncthreads();
    }

    // epilogue: scatter to g_q/g_k/g_v [b,h,token,d]; q pre-scaled by SCALE*log2e
#pragma unroll
    for (int ni = 0; ni < 8; ni++) {
        int o = nT + wn + ni * 8 + 2 * lc;
        float* dst;
        float sc = 1.f;
        if (o < 512)       { dst = g_q; sc = QSCALE; }
        else if (o < 1024) { dst = g_k; }
        else               { dst = g_v; }
        int head = (o >> 6) & 7;
        int d = o & 63;
        float b0 = bias[o], b1 = bias[o + 1];
        float* base = dst + ((size_t)(b * NHEAD + head) * NTOK) * 64 + d;
#pragma unroll
        for (int mi = 0; mi < 4; mi++) {
            int r = mT + wm + mi * 16 + lr;
            *reinterpret_cast<float2*>(base + (size_t)r * 64) =
                make_float2((acc[mi][ni][0] + b0) * sc, (acc[mi][ni][1] + b1) * sc);
            *reinterpret_cast<float2*>(base + (size_t)(r + 8) * 64) =
                make_float2((acc[mi][ni][2] + b0) * sc, (acc[mi][ni][3] + b1) * sc);
        }
    }
}

// ---------------------------------------------------------------------------
// Kernel 2: causal flash attention, FA2-style register softmax.
// BM=128 (8 warps x 16 rows), BN=64. Q fragments in registers, S in registers,
// P via per-warp smem region (old Q staging), causal tile skipping.
// ---------------------------------------------------------------------------
__global__ void __launch_bounds__(256, 2) attn_kernel()
{
    extern __shared__ unsigned sm[];
    unsigned* QP = sm;               // [128][76]  Q staging (tf32) -> later P
    unsigned* Ks = sm + 9728;        // [64][76]
    unsigned* Vs = sm + 14592;       // [64][72]
    // total 19200 words = 76800 B

    const int t = threadIdx.x, lane = t & 31, w = t >> 5;
    const int lr = lane >> 2, lc = lane & 3;
    const int qt = 7 - blockIdx.x;   // heavy blocks first
    const int h = blockIdx.y, b = blockIdx.z;

    const size_t base = (size_t)(b * NHEAD + h) * (NTOK * 64);
    const float* Qg = g_q + base + (size_t)qt * 128 * 64;
    const float* Kg = g_k + base;
    const float* Vg = g_v + base;

    const int lrow = t >> 4, lcol = (t & 15) * 4;
    // stage Q into QP
#pragma unroll
    for (int i = 0; i < 8; i++) {
        int r = lrow + i * 16;
        float4 v = *reinterpret_cast<const float4*>(Qg + r * 64 + lcol);
        *reinterpret_cast<uint4*>(&QP[r * 76 + lcol]) = f2tf4(v);
    }
    __syncthreads();

    // Q fragments -> registers (warp w owns rows 16w..16w+15)
    const int row0 = 16 * w + lr;
    const int row1 = row0 + 8;
    unsigned qf[8][4];
#pragma unroll
    for (int ks = 0; ks < 8; ks++) {
        const unsigned* p = &QP[row0 * 76 + ks * 8 + lc];
        qf[ks][0] = p[0];
        qf[ks][1] = p[8 * 76];
        qf[ks][2] = p[4];
        qf[ks][3] = p[8 * 76 + 4];
    }
    // (no barrier needed: each warp reads only its own rows, and only this
    //  warp later overwrites them with P)

    float m0 = -1e30f, m1 = -1e30f, l0 = 0.f, l1 = 0.f;
    float oacc[8][4];
#pragma unroll
    for (int i = 0; i < 8; i++)
#pragma unroll
        for (int q = 0; q < 4; q++) oacc[i][q] = 0.f;

    const int kt_last = 2 * qt + 1;

    for (int kt = 0; kt <= kt_last; kt++) {
        // stage K (ld76) and V (ld72)
        {
            const float* kg = Kg + (size_t)kt * 64 * 64;
            const float* vg = Vg + (size_t)kt * 64 * 64;
#pragma unroll
            for (int i = 0; i < 4; i++) {
                int r = lrow + i * 16;
                float4 kv = *reinterpret_cast<const float4*>(kg + r * 64 + lcol);
                *reinterpret_cast<uint4*>(&Ks[r * 76 + lcol]) = f2tf4(kv);
            }
#pragma unroll
            for (int i = 0; i < 4; i++) {
                int r = lrow + i * 16;
                float4 vv = *reinterpret_cast<const float4*>(vg + r * 64 + lcol);
                *reinterpret_cast<uint4*>(&Vs[r * 72 + lcol]) = f2tf4(vv);
            }
        }
        __syncthreads();

        const int off = kt * 64 - qt * 128;
        const int lim = min(8, max(0, ((16 * w + 15 - off) >> 3) + 1));

        if (lim > 0) {
            // ---- S = Q K^T (per-warp 16 x 64), registers only ----
            float s[8][4];
            if (off < 0) {
                // interior tile: full 8 n-tiles, no mask
#pragma unroll
                for (int nt = 0; nt < 8; nt++) {
                    float* sv = s[nt];
                    sv[0] = sv[1] = sv[2] = sv[3] = 0.f;
#pragma unroll
                    for (int ks = 0; ks < 8; ks++) {
                        unsigned bb[2];
                        const unsigned* p = &Ks[(nt * 8 + lr) * 76 + ks * 8 + lc];
                        bb[0] = p[0]; bb[1] = p[4];
                        mma8(sv, qf[ks], bb);
                    }
                }
            } else {
                // diagonal tiles: skip fully-masked n-tiles, mask partials
#pragma unroll
                for (int nt = 0; nt < 8; nt++) {
                    float* sv = s[nt];
                    if (nt < lim) {
                        sv[0] = sv[1] = sv[2] = sv[3] = 0.f;
#pragma unroll
                        for (int ks = 0; ks < 8; ks++) {
                            unsigned bb[2];
                            const unsigned* p = &Ks[(nt * 8 + lr) * 76 + ks * 8 + lc];
                            bb[0] = p[0]; bb[1] = p[4];
                            mma8(sv, qf[ks], bb);
                        }
                        int c0 = off + nt * 8 + 2 * lc;
                        if (c0 > row0)     sv[0] = -1e30f;
                        if (c0 + 1 > row0) sv[1] = -1e30f;
                        if (c0 > row1)     sv[2] = -1e30f;
                        if (c0 + 1 > row1) sv[3] = -1e30f;
                    } else {
                        sv[0] = sv[1] = sv[2] = sv[3] = -1e30f;
                    }
                }
            }

            // ---- register softmax (rows owned by quad; 2 shfls) ----
            float mx0 = -1e30f, mx1 = -1e30f;
#pragma unroll
            for (int nt = 0; nt < 8; nt++) {
                mx0 = fmaxf(mx0, fmaxf(s[nt][0], s[nt][1]));
                mx1 = fmaxf(mx1, fmaxf(s[nt][2], s[nt][3]));
            }
            mx0 = fmaxf(mx0, __shfl_xor_sync(0xffffffffu, mx0, 1));
            mx0 = fmaxf(mx0, __shfl_xor_sync(0xffffffffu, mx0, 2));
            mx1 = fmaxf(mx1, __shfl_xor_sync(0xffffffffu, mx1, 1));
            mx1 = fmaxf(mx1, __shfl_xor_sync(0xffffffffu, mx1, 2));
            float m0n = fmaxf(m0, mx0), m1n = fmaxf(m1, mx1);
            float a0 = ex2(m0 - m0n), a1 = ex2(m1 - m1n);
            m0 = m0n; m1 = m1n;

            float sum0 = 0.f, sum1 = 0.f;
#pragma unroll
            for (int nt = 0; nt < 8; nt++) {
                float e0 = ex2(s[nt][0] - m0n);
                float e1 = ex2(s[nt][1] - m0n);
                float e2 = ex2(s[nt][2] - m1n);
                float e3 = ex2(s[nt][3] - m1n);
                sum0 += e0 + e1;
                sum1 += e2 + e3;
                *reinterpret_cast<uint2*>(&QP[row0 * 76 + nt * 8 + 2 * lc]) =
                    make_uint2(f2tf(e0), f2tf(e1));
                *reinterpret_cast<uint2*>(&QP[row1 * 76 + nt * 8 + 2 * lc]) =
                    make_uint2(f2tf(e2), f2tf(e3));
            }
            sum0 += __shfl_xor_sync(0xffffffffu, sum0, 1);
            sum0 += __shfl_xor_sync(0xffffffffu, sum0, 2);
            sum1 += __shfl_xor_sync(0xffffffffu, sum1, 1);
            sum1 += __shfl_xor_sync(0xffffffffu, sum1, 2);
            l0 = l0 * a0 + sum0;
            l1 = l1 * a1 + sum1;

#pragma unroll
            for (int nt = 0; nt < 8; nt++) {
                oacc[nt][0] *= a0; oacc[nt][1] *= a0;
                oacc[nt][2] *= a1; oacc[nt][3] *= a1;
            }
            __syncwarp();

            // ---- O += P V (per-warp 16 x 64, k = 64) ----
#pragma unroll
            for (int ks = 0; ks < 8; ks++) {
                unsigned pa[4];
                const unsigned* pp = &QP[row0 * 76 + ks * 8 + lc];
                pa[0] = pp[0];
                pa[1] = pp[8 * 76];
                pa[2] = pp[4];
                pa[3] = pp[8 * 76 + 4];
#pragma unroll
                for (int nt = 0; nt < 8; nt++) {
                    unsigned bb[2];
                    const unsigned* vp = &Vs[(ks * 8 + lc) * 72 + nt * 8 + lr];
                    bb[0] = vp[0]; bb[1] = vp[4 * 72];
                    mma8(oacc[nt], pa, bb);
                }
            }
        }
        __syncthreads();   // before next kt overwrites Ks/Vs
    }

    // finalize
    float li0 = 1.f / l0, li1 = 1.f / l1;
    float* Og = g_o + base + (size_t)qt * 128 * 64;
#pragma unroll
    for (int nt = 0; nt < 8; nt++) {
        int c = nt * 8 + 2 * lc;
        *reinterpret_cast<float2*>(Og + (size_t)row0 * 64 + c) =
            make_float2(oacc[nt][0] * li0, oacc[nt][1] * li0);
        *reinterpret_cast<float2*>(Og + (size_t)row1 * 64 + c) =
            make_float2(oacc[nt][2] * li1, oacc[nt][3] * li1);
    }
}

// ---------------------------------------------------------------------------
// Kernel 3: proj GEMM. Block 128m x 256n (N=256 whole), warp 64x64, K=512.
// Double-buffered. Two-pass smem-transpose epilogue.
// ---------------------------------------------------------------------------
__global__ void proj_gemm_kernel(const float* __restrict__ pw,
                                 const float* __restrict__ pb,
                                 float* __restrict__ out)
{
    extern __shared__ unsigned smem[];
    unsigned* As = smem;            // [2][128][40] = 10240
    unsigned* Bs = smem + 10240;    // [2][256][40] = 20480

    const int b  = blockIdx.z;
    const int mT = blockIdx.x * 128;
    const int t = threadIdx.x;
    const int lane = t & 31;
    const int warp = t >> 5;
    const int wm = (warp & 1) * 64;
    const int wn = (warp >> 1) * 64;
    const int lr = lane >> 2;
    const int lc = lane & 3;

    float acc[4][8][4];
#pragma unroll
    for (int i = 0; i < 4; i++)
#pragma unroll
        for (int j = 0; j < 8; j++)
#pragma unroll
            for (int q = 0; q < 4; q++) acc[i][j][q] = 0.f;

    const int a_tok = t >> 2, a_kd = (t & 3) * 4;
    const int b_n   = t >> 2, b_k  = (t & 3) * 4;

    float4 ax[2], bx[4];
    const float* ob = g_o + (size_t)b * (NHEAD * NTOK * 64);

#pragma unroll
    for (int i = 0; i < 2; i++)
        ax[i] = *reinterpret_cast<const float4*>(
            ob + (size_t)(mT + a_tok + i * 64) * 64 + a_kd);
#pragma unroll
    for (int i = 0; i < 4; i++)
        bx[i] = *reinterpret_cast<const float4*>(pw + (size_t)(b_n + i * 64) * 512 + b_k);
    {
#pragma unroll
        for (int i = 0; i < 2; i++)
            *reinterpret_cast<uint4*>(&As[(a_tok + i * 64) * 40 + a_kd]) = f2tf4(ax[i]);
#pragma unroll
        for (int i = 0; i < 4; i++)
            *reinterpret_cast<uint4*>(&Bs[(b_n + i * 64) * 40 + b_k]) = f2tf4(bx[i]);
    }
    __syncthreads();

    for (int it = 0; it < 32; it++) {
        const unsigned* Ac = As + (it & 1) * 5120;
        const unsigned* Bc = Bs + (it & 1) * 10240;
        if (it < 31) {
            int kk = (it + 1) * 16;
            int head = kk >> 6, d0 = kk & 63;
            const float* oh = ob + (size_t)head * (NTOK * 64);
#pragma unroll
            for (int i = 0; i < 2; i++)
                ax[i] = *reinterpret_cast<const float4*>(
                    oh + (size_t)(mT + a_tok + i * 64) * 64 + d0 + a_kd);
#pragma unroll
            for (int i = 0; i < 4; i++)
                bx[i] = *reinterpret_cast<const float4*>(pw + (size_t)(b_n + i * 64) * 512 + kk + b_k);
        }
#pragma unroll
        for (int ks = 0; ks < 16; ks += 8) {
            unsigned a[4][4], bb[8][2];
#pragma unroll
            for (int mi = 0; mi < 4; mi++) {
                const unsigned* p = &Ac[(wm + mi * 16 + lr) * 40 + ks + lc];
                a[mi][0] = p[0]; a[mi][1] = p[320]; a[mi][2] = p[4]; a[mi][3] = p[324];
            }
#pragma unroll
            for (int ni = 0; ni < 8; ni++) {
                const unsigned* p = &Bc[(wn + ni * 8 + lr) * 40 + ks + lc];
                bb[ni][0] = p[0]; bb[ni][1] = p[4];
            }
#pragma unroll
            for (int mi = 0; mi < 4; mi++)
#pragma unroll
                for (int ni = 0; ni < 8; ni++)
                    mma8(acc[mi][ni], a[mi], bb[ni]);
        }
        if (it < 31) {
            unsigned* Ab = As + ((it + 1) & 1) * 5120;
            unsigned* Bb = Bs + ((it + 1) & 1) * 10240;
#pragma unroll
            for (int i = 0; i < 2; i++)
                *reinterpret_cast<uint4*>(&Ab[(a_tok + i * 64) * 40 + a_kd]) = f2tf4(ax[i]);
#pragma unroll
            for (int i = 0; i < 4; i++)
                *reinterpret_cast<uint4*>(&Bb[(b_n + i * 64) * 40 + b_k]) = f2tf4(bx[i]);
        }
        __syncthreads();
    }

    // two-pass transpose epilogue: Cs[n(128)][m(128)] ld132 overlaying As/Bs
    float* Cs = (float*)smem;
    for (int half = 0; half < 2; half++) {
        __syncthreads();
        if ((warp >> 2) == half) {
            int nb = wn - half * 128;   // 0 or 64
#pragma unroll
            for (int ni = 0; ni < 8; ni++) {
                int n = nb + ni * 8 + 2 * lc;
#pragma unroll
                for (int mi = 0; mi < 4; mi++) {
                    int m = wm + mi * 16 + lr;
                    Cs[n * 132 + m]           = acc[mi][ni][0];
                    Cs[(n + 1) * 132 + m]     = acc[mi][ni][1];
                    Cs[n * 132 + m + 8]       = acc[mi][ni][2];
                    Cs[(n + 1) * 132 + m + 8] = acc[mi][ni][3];
                }
            }
        }
        __syncthreads();
#pragma unroll
        for (int i = 0; i < 16; i++) {
            int idx = t + i * 256;
            int n = idx >> 5, mq = (idx & 31) * 4;
            int ng = half * 128 + n;
            float bi = pb[ng];
            const float* src = &Cs[n * 132 + mq];
            float4 v;
            v.x = src[0] + bi; v.y = src[1] + bi; v.z = src[2] + bi; v.w = src[3] + bi;
            *reinterpret_cast<float4*>(out + (size_t)(b * 256 + ng) * NTOK + mT + mq) = v;
        }
    }
}

// ---------------------------------------------------------------------------
extern "C" void kernel_launch(void* const* d_in, const int* in_sizes, int n_in,
                              void* d_out, int out_size)
{
    const float* x      = (const float*)d_in[0];
    const float* qkv_w  = (const float*)d_in[1];
    const float* qkv_b  = (const float*)d_in[2];
    const float* proj_w = (const float*)d_in[3];
    const float* proj_b = (const float*)d_in[4];
    float* out = (float*)d_out;

    const int qkv_smem  = (4352 + 20480) * 4;          // 99328
    const int attn_smem = 19200 * 4;                   // 76800
    const int proj_smem = (10240 + 20480) * 4;         // 122880
    cudaFuncSetAttribute(qkv_gemm_kernel, cudaFuncAttributeMaxDynamicSharedMemorySize, qkv_smem);
    cudaFuncSetAttribute(attn_kernel, cudaFuncAttributeMaxDynamicSharedMemorySize, attn_smem);
    cudaFuncSetAttribute(proj_gemm_kernel, cudaFuncAttributeMaxDynamicSharedMemorySize, proj_smem);

    qkv_gemm_kernel<<<dim3(8, 6, BATCH), 256, qkv_smem>>>(x, qkv_w, qkv_b);
    attn_kernel<<<dim3(8, NHEAD, BATCH), 256, attn_smem>>>();
    proj_gemm_kernel<<<dim3(8, 1, BATCH), 256, proj_smem>>>(proj_w, proj_b, out);
}

// round 7
// speedup vs baseline: 5.4176x; 1.7142x over previous
#include <cuda_runtime.h>
#include <cuda_fp16.h>
#include <cstdint>

#define BATCH   16
#define IN_CH   256
#define NTOK    1024
#define NHEAD   8
// SCALE * log2(e): softmax done in exp2 domain
#define QSCALE  0.18033688f

// Scratch: [B, H, N, D] in half
__device__ __align__(16) __half g_q[BATCH * NHEAD * NTOK * 64];
__device__ __align__(16) __half g_k[BATCH * NHEAD * NTOK * 64];
__device__ __align__(16) __half g_v[BATCH * NHEAD * NTOK * 64];
__device__ __align__(16) __half g_o[BATCH * NHEAD * NTOK * 64];

__device__ __forceinline__ unsigned f2h2(float lo, float hi) {
    unsigned r;
    asm("cvt.rn.f16x2.f32 %0, %1, %2;" : "=r"(r) : "f"(hi), "f"(lo));
    return r;
}
__device__ __forceinline__ float ex2(float x) {
    float r;
    asm("ex2.approx.f32 %0, %1;" : "=f"(r) : "f"(x));
    return r;
}
__device__ __forceinline__ uint32_t smem_u32(const void* p) {
    uint32_t a;
    asm("{ .reg .u64 t; cvta.to.shared.u64 t, %1; cvt.u32.u64 %0, t; }" : "=r"(a) : "l"(p));
    return a;
}
__device__ __forceinline__ void mma16(float* d, const unsigned* a, const unsigned* b) {
    asm volatile(
        "mma.sync.aligned.m16n8k16.row.col.f32.f16.f16.f32 "
        "{%0,%1,%2,%3}, {%4,%5,%6,%7}, {%8,%9}, {%0,%1,%2,%3};\n"
        : "+f"(d[0]), "+f"(d[1]), "+f"(d[2]), "+f"(d[3])
        : "r"(a[0]), "r"(a[1]), "r"(a[2]), "r"(a[3]), "r"(b[0]), "r"(b[1]));
}
#define CPA16(dst, src) \
    asm volatile("cp.async.cg.shared.global [%0], [%1], 16;" :: "r"(dst), "l"(src))
#define CP_COMMIT() asm volatile("cp.async.commit_group;" ::: "memory")
#define CP_WAIT0()  asm volatile("cp.async.wait_group 0;" ::: "memory")

// ---------------------------------------------------------------------------
// Kernel 1: QKV GEMM fp16. Block 128m x 128n, BK=32, 8 warps (2m x 4n),
// warp 64x32. As [m][k] half2-words ld20, XOR-swizzled cols (transposed store
// from x[c][m]). Bs [n][k] ld20 plain. Double-buffered.
// ---------------------------------------------------------------------------
__global__ void __launch_bounds__(256, 2) qkv_gemm_kernel(
    const float* __restrict__ x, const float* __restrict__ w,
    const float* __restrict__ bias)
{
    extern __shared__ unsigned smem[];
    unsigned* As = smem;            // [2][128][20] words
    unsigned* Bs = smem + 5120;     // [2][128][20]

    const int b  = blockIdx.z;
    const int mT = blockIdx.x * 128;
    const int nT = blockIdx.y * 128;
    const int t = threadIdx.x, lane = t & 31, warp = t >> 5;
    const int wm = (warp & 1) * 64;
    const int wn = (warp >> 1) * 32;
    const int lr = lane >> 2, lc = lane & 3;

    const float* xb = x + (size_t)b * (IN_CH * NTOK);

    float acc[4][4][4];
#pragma unroll
    for (int i = 0; i < 4; i++)
#pragma unroll
        for (int j = 0; j < 4; j++)
#pragma unroll
            for (int q = 0; q < 4; q++) acc[i][j][q] = 0.f;

    const int acp = t >> 4, amq = t & 15;   // A loader: k-wordcol, m-quad base
    const int bn8 = t >> 3, bkf = t & 7;    // B loader

    float4 ax[2][2], bx4[4];

#define LDA(kk) do { \
    _Pragma("unroll") \
    for (int j = 0; j < 2; j++) { \
        int mq = amq + 16 * j; \
        ax[j][0] = *(const float4*)(xb + (size_t)((kk) + 2 * acp) * NTOK + mT + 4 * mq); \
        ax[j][1] = *(const float4*)(xb + (size_t)((kk) + 2 * acp + 1) * NTOK + mT + 4 * mq); \
    } } while (0)
#define LDB_Q(kk) do { \
    _Pragma("unroll") \
    for (int i = 0; i < 4; i++) \
        bx4[i] = *(const float4*)(w + (size_t)(nT + bn8 + 32 * i) * IN_CH + (kk) + bkf * 4); \
    } while (0)
#define STA(Ab) do { \
    _Pragma("unroll") \
    for (int j = 0; j < 2; j++) { \
        int mq = amq + 16 * j; \
        const float* A0 = &ax[j][0].x; \
        const float* A1 = &ax[j][1].x; \
        int col = acp ^ (mq & 15); \
        _Pragma("unroll") \
        for (int i = 0; i < 4; i++) \
            (Ab)[(4 * mq + i) * 20 + col] = f2h2(A0[i], A1[i]); \
    } } while (0)
#define STB_Q(Bb) do { \
    _Pragma("unroll") \
    for (int i = 0; i < 4; i++) { \
        int n = bn8 + 32 * i; \
        *(uint2*)&(Bb)[n * 20 + bkf * 2] = \
            make_uint2(f2h2(bx4[i].x, bx4[i].y), f2h2(bx4[i].z, bx4[i].w)); \
    } } while (0)

    LDA(0); LDB_Q(0); STA(As); STB_Q(Bs);
    __syncthreads();

    int s0[4], s1[4];
#pragma unroll
    for (int mi = 0; mi < 4; mi++) {
        int m0 = wm + 16 * mi + lr;
        s0[mi] = (m0 >> 2) & 15;
        s1[mi] = ((m0 + 8) >> 2) & 15;
    }

    for (int it = 0; it < 8; it++) {
        const unsigned* Ac = As + (it & 1) * 2560;
        const unsigned* Bc = Bs + (it & 1) * 2560;
        if (it < 7) { LDA((it + 1) * 32); LDB_Q((it + 1) * 32); }
#pragma unroll
        for (int kg = 0; kg < 2; kg++) {
            unsigned a[4][4], bb[4][2];
            int k0 = kg * 8 + lc;
#pragma unroll
            for (int mi = 0; mi < 4; mi++) {
                int m0 = (wm + 16 * mi + lr) * 20;
                int m1 = m0 + 160;
                a[mi][0] = Ac[m0 + (k0 ^ s0[mi])];
                a[mi][1] = Ac[m1 + (k0 ^ s1[mi])];
                a[mi][2] = Ac[m0 + ((k0 + 4) ^ s0[mi])];
                a[mi][3] = Ac[m1 + ((k0 + 4) ^ s1[mi])];
            }
#pragma unroll
            for (int ni = 0; ni < 4; ni++) {
                const unsigned* p = &Bc[(wn + ni * 8 + lr) * 20 + k0];
                bb[ni][0] = p[0]; bb[ni][1] = p[4];
            }
#pragma unroll
            for (int mi = 0; mi < 4; mi++)
#pragma unroll
                for (int ni = 0; ni < 4; ni++)
                    mma16(acc[mi][ni], a[mi], bb[ni]);
        }
        if (it < 7) {
            unsigned* An = As + ((it + 1) & 1) * 2560;
            unsigned* Bn = Bs + ((it + 1) & 1) * 2560;
            STA(An); STB_Q(Bn);
        }
        __syncthreads();
    }

    // epilogue -> half g_q/g_k/g_v [b,h,tok,d]; q pre-scaled by SCALE*log2e
#pragma unroll
    for (int ni = 0; ni < 4; ni++) {
        int o = nT + wn + ni * 8 + 2 * lc;
        __half* dst;
        float sc = 1.f;
        if (o < 512)       { dst = g_q; sc = QSCALE; }
        else if (o < 1024) { dst = g_k; }
        else               { dst = g_v; }
        int head = (o >> 6) & 7, d = o & 63;
        float b0 = bias[o], b1 = bias[o + 1];
        __half* base = dst + ((size_t)(b * NHEAD + head) * NTOK) * 64 + d;
#pragma unroll
        for (int mi = 0; mi < 4; mi++) {
            int r = mT + wm + mi * 16 + lr;
            *(unsigned*)(base + (size_t)r * 64) =
                f2h2((acc[mi][ni][0] + b0) * sc, (acc[mi][ni][1] + b1) * sc);
            *(unsigned*)(base + (size_t)(r + 8) * 64) =
                f2h2((acc[mi][ni][2] + b0) * sc, (acc[mi][ni][3] + b1) * sc);
        }
    }
}

// ---------------------------------------------------------------------------
// Kernel 2: causal flash attention fp16, FA2 register softmax.
// BM=128 (8 warps x 16 rows), BN=64. cp.async K, double-buffered K/V,
// V transposed+swizzled in smem, 1 barrier per key tile.
// ---------------------------------------------------------------------------
__global__ void __launch_bounds__(256, 2) attn_kernel()
{
    extern __shared__ unsigned sm[];
    unsigned* QP = sm;                 // [128][36] Q staging -> P
    unsigned* Ks = sm + 4608;          // [2][64][36]
    unsigned* Vt = sm + 4608 + 4608;   // [2][64][36] transposed [dv][key]
    const uint32_t sb = smem_u32(sm);

    const int t = threadIdx.x, lane = t & 31, w = t >> 5;
    const int lr = lane >> 2, lc = lane & 3;
    const int qt = 7 - blockIdx.x;     // heavy blocks first
    const int h = blockIdx.y, b = blockIdx.z;

    const size_t base = (size_t)(b * NHEAD + h) * (NTOK * 64);
    const __half* Qg = g_q + base + (size_t)qt * 128 * 64;
    const __half* Kg = g_k + base;
    const __half* Vg = g_v + base;

    const int r8 = t >> 3, c8 = t & 7;

    // stage Q (cp.async) + K0 (cp.async)
#pragma unroll
    for (int i = 0; i < 4; i++)
        CPA16(sb + (((r8 + 32 * i) * 36 + c8 * 4) << 2),
              Qg + (size_t)(r8 + 32 * i) * 64 + c8 * 8);
#pragma unroll
    for (int i = 0; i < 2; i++)
        CPA16(sb + ((4608 + (r8 + 32 * i) * 36 + c8 * 4) << 2),
              Kg + (size_t)(r8 + 32 * i) * 64 + c8 * 8);
    CP_COMMIT();

    // V0 -> regs
    const int vtp = t >> 4, vd4 = (t & 15) * 4, vs = t & 15;
    uint2 va[2], vb[2];
#pragma unroll
    for (int i = 0; i < 2; i++) {
        int tk = 2 * (vtp + 16 * i);
        va[i] = *(const uint2*)(Vg + (size_t)tk * 64 + vd4);
        vb[i] = *(const uint2*)(Vg + (size_t)(tk + 1) * 64 + vd4);
    }

    CP_WAIT0();
    __syncthreads();

    // Q fragments -> regs (warp w owns rows 16w..16w+15)
    const int row0 = 16 * w + lr;
    const int row1 = row0 + 8;
    unsigned qf[4][4];
#pragma unroll
    for (int g = 0; g < 4; g++) {
        qf[g][0] = QP[row0 * 36 + 8 * g + lc];
        qf[g][1] = QP[row1 * 36 + 8 * g + lc];
        qf[g][2] = QP[row0 * 36 + 8 * g + lc + 4];
        qf[g][3] = QP[row1 * 36 + 8 * g + lc + 4];
    }

    float m0 = -1e30f, m1 = -1e30f, l0 = 0.f, l1 = 0.f;
    float oacc[8][4];
#pragma unroll
    for (int i = 0; i < 8; i++)
#pragma unroll
        for (int q = 0; q < 4; q++) oacc[i][q] = 0.f;

    const int kt_last = 2 * qt + 1;

    for (int kt = 0; kt <= kt_last; kt++) {
        const int buf = kt & 1;
        unsigned* Kb = Ks + buf * 2304;
        unsigned* Vb = Vt + buf * 2304;

        // store V regs (transpose + swizzle)
#pragma unroll
        for (int i = 0; i < 2; i++) {
            int tp = vtp + 16 * i;
            int col = tp ^ vs;
            Vb[(vd4 + 0) * 36 + col] = __byte_perm(va[i].x, vb[i].x, 0x5410);
            Vb[(vd4 + 1) * 36 + col] = __byte_perm(va[i].x, vb[i].x, 0x7632);
            Vb[(vd4 + 2) * 36 + col] = __byte_perm(va[i].y, vb[i].y, 0x5410);
            Vb[(vd4 + 3) * 36 + col] = __byte_perm(va[i].y, vb[i].y, 0x7632);
        }
        if (kt > 0) CP_WAIT0();
        __syncthreads();   // publish K[buf], V[buf]

        if (kt < kt_last) {
            const __half* kg = Kg + (size_t)(kt + 1) * 64 * 64;
            const __half* vg = Vg + (size_t)(kt + 1) * 64 * 64;
            int nb = buf ^ 1;
#pragma unroll
            for (int i = 0; i < 2; i++)
                CPA16(sb + ((4608 + nb * 2304 + (r8 + 32 * i) * 36 + c8 * 4) << 2),
                      kg + (size_t)(r8 + 32 * i) * 64 + c8 * 8);
            CP_COMMIT();
#pragma unroll
            for (int i = 0; i < 2; i++) {
                int tk = 2 * (vtp + 16 * i);
                va[i] = *(const uint2*)(vg + (size_t)tk * 64 + vd4);
                vb[i] = *(const uint2*)(vg + (size_t)(tk + 1) * 64 + vd4);
            }
        }

        const int off = kt * 64 - qt * 128;
        const int lim = min(8, max(0, ((16 * w + 15 - off) >> 3) + 1));

        if (lim > 0) {
            // ---- S = Q K^T (16 x 64 per warp) ----
            float s[8][4];
            if (off < 0) {
#pragma unroll
                for (int nt = 0; nt < 8; nt++) {
                    float* sv = s[nt];
                    sv[0] = sv[1] = sv[2] = sv[3] = 0.f;
#pragma unroll
                    for (int g = 0; g < 4; g++) {
                        unsigned bb[2];
                        const unsigned* p = &Kb[(nt * 8 + lr) * 36 + 8 * g + lc];
                        bb[0] = p[0]; bb[1] = p[4];
                        mma16(sv, qf[g], bb);
                    }
                }
            } else {
#pragma unroll
                for (int nt = 0; nt < 8; nt++) {
                    float* sv = s[nt];
                    if (nt < lim) {
                        sv[0] = sv[1] = sv[2] = sv[3] = 0.f;
#pragma unroll
                        for (int g = 0; g < 4; g++) {
                            unsigned bb[2];
                            const unsigned* p = &Kb[(nt * 8 + lr) * 36 + 8 * g + lc];
                            bb[0] = p[0]; bb[1] = p[4];
                            mma16(sv, qf[g], bb);
                        }
                        int c0 = off + nt * 8 + 2 * lc;
                        if (c0 > row0)     sv[0] = -1e30f;
                        if (c0 + 1 > row0) sv[1] = -1e30f;
                        if (c0 > row1)     sv[2] = -1e30f;
                        if (c0 + 1 > row1) sv[3] = -1e30f;
                    } else {
                        sv[0] = sv[1] = sv[2] = sv[3] = -1e30f;
                    }
                }
            }

            // ---- register softmax (exp2 domain) ----
            float mx0 = -1e30f, mx1 = -1e30f;
#pragma unroll
            for (int nt = 0; nt < 8; nt++) {
                mx0 = fmaxf(mx0, fmaxf(s[nt][0], s[nt][1]));
                mx1 = fmaxf(mx1, fmaxf(s[nt][2], s[nt][3]));
            }
            mx0 = fmaxf(mx0, __shfl_xor_sync(0xffffffffu, mx0, 1));
            mx0 = fmaxf(mx0, __shfl_xor_sync(0xffffffffu, mx0, 2));
            mx1 = fmaxf(mx1, __shfl_xor_sync(0xffffffffu, mx1, 1));
            mx1 = fmaxf(mx1, __shfl_xor_sync(0xffffffffu, mx1, 2));
            float m0n = fmaxf(m0, mx0), m1n = fmaxf(m1, mx1);
            float a0 = ex2(m0 - m0n), a1 = ex2(m1 - m1n);
            m0 = m0n; m1 = m1n;

            float sum0 = 0.f, sum1 = 0.f;
#pragma unroll
            for (int nt = 0; nt < 8; nt++) {
                float e0 = ex2(s[nt][0] - m0n);
                float e1 = ex2(s[nt][1] - m0n);
                float e2 = ex2(s[nt][2] - m1n);
                float e3 = ex2(s[nt][3] - m1n);
                sum0 += e0 + e1;
                sum1 += e2 + e3;
                QP[row0 * 36 + nt * 4 + lc] = f2h2(e0, e1);
                QP[row1 * 36 + nt * 4 + lc] = f2h2(e2, e3);
            }
            sum0 += __shfl_xor_sync(0xffffffffu, sum0, 1);
            sum0 += __shfl_xor_sync(0xffffffffu, sum0, 2);
            sum1 += __shfl_xor_sync(0xffffffffu, sum1, 1);
            sum1 += __shfl_xor_sync(0xffffffffu, sum1, 2);
            l0 = l0 * a0 + sum0;
            l1 = l1 * a1 + sum1;

#pragma unroll
            for (int nt = 0; nt < 8; nt++) {
                oacc[nt][0] *= a0; oacc[nt][1] *= a0;
                oacc[nt][2] *= a1; oacc[nt][3] *= a1;
            }
            __syncwarp();

            // ---- O += P V ----
#pragma unroll
            for (int g = 0; g < 4; g++) {
                unsigned pa[4];
                pa[0] = QP[row0 * 36 + 8 * g + lc];
                pa[1] = QP[row1 * 36 + 8 * g + lc];
                pa[2] = QP[row0 * 36 + 8 * g + lc + 4];
                pa[3] = QP[row1 * 36 + 8 * g + lc + 4];
#pragma unroll
                for (int nt = 0; nt < 8; nt++) {
                    int dv = nt * 8 + lr;
                    int sdv = (dv >> 2) & 15;
                    unsigned bb[2];
                    bb[0] = Vb[dv * 36 + ((8 * g + lc) ^ sdv)];
                    bb[1] = Vb[dv * 36 + ((8 * g + lc + 4) ^ sdv)];
                    mma16(oacc[nt], pa, bb);
                }
            }
        }
    }

    // finalize -> half g_o
    float li0 = 1.f / l0, li1 = 1.f / l1;
    __half* Og = g_o + base + (size_t)qt * 128 * 64;
#pragma unroll
    for (int nt = 0; nt < 8; nt++) {
        int c = nt * 8 + 2 * lc;
        *(unsigned*)(Og + (size_t)row0 * 64 + c) = f2h2(oacc[nt][0] * li0, oacc[nt][1] * li0);
        *(unsigned*)(Og + (size_t)row1 * 64 + c) = f2h2(oacc[nt][2] * li1, oacc[nt][3] * li1);
    }
}

// ---------------------------------------------------------------------------
// Kernel 3: proj GEMM fp16. Block 128m x 128n, BK=32, warp 64x32, K=512.
// A (g_o half) via cp.async; B (pw fp32) manual cvt. Transpose epilogue.
// ---------------------------------------------------------------------------
__global__ void __launch_bounds__(256, 2) proj_gemm_kernel(
    const float* __restrict__ pw, const float* __restrict__ pb,
    float* __restrict__ out)
{
    extern __shared__ unsigned smem[];
    unsigned* As = smem;            // [2][128][20]
    unsigned* Bs = smem + 5120;     // [2][128][20]
    const uint32_t sb = smem_u32(smem);

    const int b  = blockIdx.z;
    const int mT = blockIdx.x * 128;
    const int nT = blockIdx.y * 128;
    const int t = threadIdx.x, lane = t & 31, warp = t >> 5;
    const int wm = (warp & 1) * 64;
    const int wn = (warp >> 1) * 32;
    const int lr = lane >> 2, lc = lane & 3;

    const __half* ob = g_o + (size_t)b * (NHEAD * NTOK * 64);

    float acc[4][4][4];
#pragma unroll
    for (int i = 0; i < 4; i++)
#pragma unroll
        for (int j = 0; j < 4; j++)
#pragma unroll
            for (int q = 0; q < 4; q++) acc[i][j][q] = 0.f;

    const int ar = t >> 2, aq = t & 3;
    const int bn8 = t >> 3, bkf = t & 7;
    float4 bx4[4];

#define ISSUE_A(kk, bufw) do { \
    int head = (kk) >> 6, d0 = (kk) & 63; \
    const __half* src = ob + (size_t)head * (NTOK * 64); \
    _Pragma("unroll") \
    for (int i = 0; i < 2; i++) { \
        int r = ar + 64 * i; \
        CPA16(sb + (((bufw) + r * 20 + aq * 4) << 2), \
              src + (size_t)(mT + r) * 64 + d0 + aq * 8); \
    } CP_COMMIT(); } while (0)
#define LDB_P(kk) do { \
    _Pragma("unroll") \
    for (int i = 0; i < 4; i++) \
        bx4[i] = *(const float4*)(pw + (size_t)(nT + bn8 + 32 * i) * 512 + (kk) + bkf * 4); \
    } while (0)
#define STB_P(Bb) do { \
    _Pragma("unroll") \
    for (int i = 0; i < 4; i++) { \
        int n = bn8 + 32 * i; \
        *(uint2*)&(Bb)[n * 20 + bkf * 2] = \
            make_uint2(f2h2(bx4[i].x, bx4[i].y), f2h2(bx4[i].z, bx4[i].w)); \
    } } while (0)

    ISSUE_A(0, 0);
    LDB_P(0);
    STB_P(Bs);
    CP_WAIT0();
    __syncthreads();

    for (int it = 0; it < 16; it++) {
        const unsigned* Ac = As + (it & 1) * 2560;
        const unsigned* Bc = Bs + (it & 1) * 2560;
        if (it < 15) {
            ISSUE_A((it + 1) * 32, ((it + 1) & 1) * 2560);
            LDB_P((it + 1) * 32);
        }
#pragma unroll
        for (int kg = 0; kg < 2; kg++) {
            unsigned a[4][4], bb[4][2];
            int k0 = kg * 8 + lc;
#pragma unroll
            for (int mi = 0; mi < 4; mi++) {
                const unsigned* p = &Ac[(wm + 16 * mi + lr) * 20 + k0];
                a[mi][0] = p[0]; a[mi][1] = p[160]; a[mi][2] = p[4]; a[mi][3] = p[164];
            }
#pragma unroll
            for (int ni = 0; ni < 4; ni++) {
                const unsigned* p = &Bc[(wn + ni * 8 + lr) * 20 + k0];
                bb[ni][0] = p[0]; bb[ni][1] = p[4];
            }
#pragma unroll
            for (int mi = 0; mi < 4; mi++)
#pragma unroll
                for (int ni = 0; ni < 4; ni++)
                    mma16(acc[mi][ni], a[mi], bb[ni]);
        }
        if (it < 15) {
            unsigned* Bn = Bs + ((it + 1) & 1) * 2560;
            STB_P(Bn);
            CP_WAIT0();
        }
        __syncthreads();
    }

    // transpose epilogue through smem: Cs[n][m] ld132 (float)
    float* Cs = (float*)smem;
#pragma unroll
    for (int ni = 0; ni < 4; ni++) {
        int n = wn + ni * 8 + 2 * lc;
#pragma unroll
        for (int mi = 0; mi < 4; mi++) {
            int m = wm + mi * 16 + lr;
            Cs[n * 132 + m]           = acc[mi][ni][0];
            Cs[(n + 1) * 132 + m]     = acc[mi][ni][1];
            Cs[n * 132 + m + 8]       = acc[mi][ni][2];
            Cs[(n + 1) * 132 + m + 8] = acc[mi][ni][3];
        }
    }
    __syncthreads();

#pragma unroll
    for (int i = 0; i < 16; i++) {
        int idx = t + i * 256;
        int n = idx >> 5, mq = (idx & 31) * 4;
        float bi = pb[nT + n];
        const float* src = &Cs[n * 132 + mq];
        float4 v;
        v.x = src[0] + bi; v.y = src[1] + bi; v.z = src[2] + bi; v.w = src[3] + bi;
        *(float4*)(out + (size_t)(b * 256 + nT + n) * NTOK + mT + mq) = v;
    }
}

// ---------------------------------------------------------------------------
extern "C" void kernel_launch(void* const* d_in, const int* in_sizes, int n_in,
                              void* d_out, int out_size)
{
    const float* x      = (const float*)d_in[0];
    const float* qkv_w  = (const float*)d_in[1];
    const float* qkv_b  = (const float*)d_in[2];
    const float* proj_w = (const float*)d_in[3];
    const float* proj_b = (const float*)d_in[4];
    float* out = (float*)d_out;

    const int qkv_smem  = 10240 * 4;   // 40960
    const int attn_smem = 13824 * 4;   // 55296
    const int proj_smem = 128 * 132 * 4;  // 67584 (epilogue dominates)
    cudaFuncSetAttribute(qkv_gemm_kernel, cudaFuncAttributeMaxDynamicSharedMemorySize, qkv_smem);
    cudaFuncSetAttribute(attn_kernel, cudaFuncAttributeMaxDynamicSharedMemorySize, attn_smem);
    cudaFuncSetAttribute(proj_gemm_kernel, cudaFuncAttributeMaxDynamicSharedMemorySize, proj_smem);

    qkv_gemm_kernel<<<dim3(8, 12, BATCH), 256, qkv_smem>>>(x, qkv_w, qkv_b);
    attn_kernel<<<dim3(8, NHEAD, BATCH), 256, attn_smem>>>();
    proj_gemm_kernel<<<dim3(8, 2, BATCH), 256, proj_smem>>>(proj_w, proj_b, out);
}

// round 8
// speedup vs baseline: 6.5871x; 1.2159x over previous
#include <cuda_runtime.h>
#include <cuda_fp16.h>
#include <cstdint>

#define BATCH   16
#define IN_CH   256
#define NTOK    1024
#define NHEAD   8
// SCALE * log2(e): softmax done in exp2 domain
#define QSCALE  0.18033688f

// Scratch
__device__ __align__(16) __half g_x[BATCH * IN_CH * NTOK];     // x in half
__device__ __align__(16) __half g_w[1536 * IN_CH];             // qkv_w half
__device__ __align__(16) __half g_pw[256 * 512];               // proj_w half
__device__ __align__(16) __half g_q[BATCH * NHEAD * NTOK * 64];
__device__ __align__(16) __half g_k[BATCH * NHEAD * NTOK * 64];
__device__ __align__(16) __half g_v[BATCH * NHEAD * NTOK * 64];
__device__ __align__(16) __half g_o[BATCH * NHEAD * NTOK * 64];

__device__ __forceinline__ unsigned f2h2(float lo, float hi) {
    unsigned r;
    asm("cvt.rn.f16x2.f32 %0, %1, %2;" : "=r"(r) : "f"(hi), "f"(lo));
    return r;
}
__device__ __forceinline__ float ex2(float x) {
    float r;
    asm("ex2.approx.f32 %0, %1;" : "=f"(r) : "f"(x));
    return r;
}
__device__ __forceinline__ uint32_t smem_u32(const void* p) {
    uint32_t a;
    asm("{ .reg .u64 t; cvta.to.shared.u64 t, %1; cvt.u32.u64 %0, t; }" : "=r"(a) : "l"(p));
    return a;
}
__device__ __forceinline__ void mma16(float* d, const unsigned* a, const unsigned* b) {
    asm volatile(
        "mma.sync.aligned.m16n8k16.row.col.f32.f16.f16.f32 "
        "{%0,%1,%2,%3}, {%4,%5,%6,%7}, {%8,%9}, {%0,%1,%2,%3};\n"
        : "+f"(d[0]), "+f"(d[1]), "+f"(d[2]), "+f"(d[3])
        : "r"(a[0]), "r"(a[1]), "r"(a[2]), "r"(a[3]), "r"(b[0]), "r"(b[1]));
}
#define LDSM4(r0, r1, r2, r3, addr) \
    asm volatile("ldmatrix.sync.aligned.m8n8.x4.shared.b16 {%0,%1,%2,%3}, [%4];" \
        : "=r"(r0), "=r"(r1), "=r"(r2), "=r"(r3) : "r"(addr))
#define LDSM4T(r0, r1, r2, r3, addr) \
    asm volatile("ldmatrix.sync.aligned.m8n8.x4.trans.shared.b16 {%0,%1,%2,%3}, [%4];" \
        : "=r"(r0), "=r"(r1), "=r"(r2), "=r"(r3) : "r"(addr))
#define CPA16(dst, src) \
    asm volatile("cp.async.cg.shared.global [%0], [%1], 16;" :: "r"(dst), "l"(src))
#define CP_COMMIT() asm volatile("cp.async.commit_group;" ::: "memory")
#define CP_WAIT0()  asm volatile("cp.async.wait_group 0;" ::: "memory")

// ---------------------------------------------------------------------------
// Kernel 0: fp32 -> fp16 pre-convert (x, qkv_w, proj_w). One float4/thread.
// ---------------------------------------------------------------------------
#define X_F4   1048576            // 16*256*1024 / 4
#define W_F4   98304              // 1536*256 / 4
#define PW_F4  32768              // 256*512 / 4
__global__ void cvt_kernel(const float* __restrict__ x,
                           const float* __restrict__ w,
                           const float* __restrict__ pw)
{
    int i = blockIdx.x * 256 + threadIdx.x;
    const float4* src;
    __half* dst;
    int j;
    if (i < X_F4)            { src = (const float4*)x;  dst = g_x;  j = i; }
    else if (i < X_F4 + W_F4){ src = (const float4*)w;  dst = g_w;  j = i - X_F4; }
    else                     { src = (const float4*)pw; dst = g_pw; j = i - X_F4 - W_F4; }
    float4 v = src[j];
    *(uint2*)(dst + 4 * (size_t)j) = make_uint2(f2h2(v.x, v.y), f2h2(v.z, v.w));
}

// ---------------------------------------------------------------------------
// Kernel 1: QKV GEMM fp16. Block 128m x 128n, BK=32, 8 warps (2m x 4n),
// warp 64x32. A tile [k32][m128] halves pitch 272B (ldmatrix.trans),
// B tile [n128][k32] pitch 80B. Pure cp.async + ldmatrix. Double-buffered.
// ---------------------------------------------------------------------------
__global__ void __launch_bounds__(256, 2) qkv_gemm_kernel(
    const float* __restrict__ bias)
{
    extern __shared__ char smem[];
    const uint32_t sb = smem_u32(smem);
    const uint32_t Ab0 = sb;             // 2 x 32*272 = 17408
    const uint32_t Bb0 = sb + 17408;     // 2 x 128*80 = 20480

    const int b  = blockIdx.z;
    const int mT = blockIdx.x * 128;
    const int nT = blockIdx.y * 128;
    const int t = threadIdx.x, lane = t & 31, warp = t >> 5;
    const int wm = (warp & 1) * 64;
    const int wn = (warp >> 1) * 32;
    const int lr = lane >> 2, lc = lane & 3;
    const int l7 = lane & 7, l8 = (lane >> 3) & 1, l16 = lane >> 4;

    const __half* xb = g_x + (size_t)b * (IN_CH * NTOK);

    float acc[4][4][4];
#pragma unroll
    for (int i = 0; i < 4; i++)
#pragma unroll
        for (int j = 0; j < 4; j++)
#pragma unroll
            for (int q = 0; q < 4; q++) acc[i][j][q] = 0.f;

    // loaders
    const int a_k = t >> 3, a_c = t & 7;     // A: k-row, chunk pair
    const int b_n = t >> 1, b_c = t & 1;     // B: n-row, chunk pair
#define QKV_ISSUE(kk, buf) do { \
    uint32_t Ad = Ab0 + (buf) * 8704, Bd = Bb0 + (buf) * 10240; \
    _Pragma("unroll") \
    for (int i = 0; i < 2; i++) \
        CPA16(Ad + a_k * 272 + (a_c * 2 + i) * 16, \
              xb + (size_t)((kk) + a_k) * NTOK + mT + (a_c * 2 + i) * 8); \
    _Pragma("unroll") \
    for (int i = 0; i < 2; i++) \
        CPA16(Bd + b_n * 80 + (b_c * 2 + i) * 16, \
              g_w + (size_t)(nT + b_n) * IN_CH + (kk) + (b_c * 2 + i) * 8); \
    CP_COMMIT(); } while (0)

    // fragment address lane-parts (bytes)
    const uint32_t aAl = (uint32_t)((l7 + 8 * l16) * 272 + 16 * l8 + wm * 2);
    const uint32_t aBl = (uint32_t)((wn + l7 + 8 * l16) * 80 + 16 * l8);

    QKV_ISSUE(0, 0);
    CP_WAIT0();
    __syncthreads();

    for (int it = 0; it < 8; it++) {
        const int buf = it & 1;
        if (it < 7) QKV_ISSUE((it + 1) * 32, buf ^ 1);
        const uint32_t Ac = Ab0 + buf * 8704 + aAl;
        const uint32_t Bc = Bb0 + buf * 10240 + aBl;
#pragma unroll
        for (int kg = 0; kg < 2; kg++) {
            unsigned a[4][4], bb[4][2];
#pragma unroll
            for (int mi = 0; mi < 4; mi++)
                LDSM4T(a[mi][0], a[mi][1], a[mi][2], a[mi][3],
                       Ac + kg * 4352 + mi * 32);
#pragma unroll
            for (int ntp = 0; ntp < 2; ntp++)
                LDSM4(bb[2 * ntp][0], bb[2 * ntp][1], bb[2 * ntp + 1][0], bb[2 * ntp + 1][1],
                      Bc + ntp * 1280 + kg * 32);
#pragma unroll
            for (int mi = 0; mi < 4; mi++)
#pragma unroll
                for (int ni = 0; ni < 4; ni++)
                    mma16(acc[mi][ni], a[mi], bb[ni]);
        }
        if (it < 7) CP_WAIT0();
        __syncthreads();
    }

    // epilogue -> half g_q/g_k/g_v [b,h,tok,d]; q pre-scaled by SCALE*log2e
#pragma unroll
    for (int ni = 0; ni < 4; ni++) {
        int o = nT + wn + ni * 8 + 2 * lc;
        __half* dst;
        float sc = 1.f;
        if (o < 512)       { dst = g_q; sc = QSCALE; }
        else if (o < 1024) { dst = g_k; }
        else               { dst = g_v; }
        int head = (o >> 6) & 7, d = o & 63;
        float b0 = bias[o], b1 = bias[o + 1];
        __half* base = dst + ((size_t)(b * NHEAD + head) * NTOK) * 64 + d;
#pragma unroll
        for (int mi = 0; mi < 4; mi++) {
            int r = mT + wm + mi * 16 + lr;
            *(unsigned*)(base + (size_t)r * 64) =
                f2h2((acc[mi][ni][0] + b0) * sc, (acc[mi][ni][1] + b1) * sc);
            *(unsigned*)(base + (size_t)(r + 8) * 64) =
                f2h2((acc[mi][ni][2] + b0) * sc, (acc[mi][ni][3] + b1) * sc);
        }
    }
}

// ---------------------------------------------------------------------------
// Kernel 2: causal flash attention fp16, FA2 register softmax + ldmatrix.
// BM=128 (8 warps x 16 rows), BN=64. All staging via cp.async (K/V double-
// buffered); V kept [key][dv], transposed by ldmatrix.trans. Pitch 144B.
// ---------------------------------------------------------------------------
__global__ void __launch_bounds__(256, 2) attn_kernel()
{
    extern __shared__ char smem[];
    const uint32_t sb = smem_u32(smem);
    const uint32_t QPb = sb;             // [128][72h] = 18432
    const uint32_t Kb0 = sb + 18432;     // 2 x [64][72h] = 18432
    const uint32_t Vb0 = sb + 36864;     // 2 x [64][72h] = 18432
    unsigned* QP32 = (unsigned*)smem;

    const int t = threadIdx.x, lane = t & 31, w = t >> 5;
    const int lr = lane >> 2, lc = lane & 3;
    const int l7 = lane & 7, l8 = (lane >> 3) & 1, l16 = lane >> 4;
    const int qt = 7 - blockIdx.x;       // heavy blocks first
    const int h = blockIdx.y, b = blockIdx.z;

    const size_t base = (size_t)(b * NHEAD + h) * (NTOK * 64);
    const __half* Qg = g_q + base + (size_t)qt * 128 * 64;
    const __half* Kg = g_k + base;
    const __half* Vg = g_v + base;

    const int r8 = t >> 3, c8 = t & 7;

    // prologue: Q + K0 + V0 via cp.async
#pragma unroll
    for (int i = 0; i < 4; i++)
        CPA16(QPb + (r8 + 32 * i) * 144 + c8 * 16, Qg + (size_t)(r8 + 32 * i) * 64 + c8 * 8);
#pragma unroll
    for (int i = 0; i < 2; i++)
        CPA16(Kb0 + (r8 + 32 * i) * 144 + c8 * 16, Kg + (size_t)(r8 + 32 * i) * 64 + c8 * 8);
#pragma unroll
    for (int i = 0; i < 2; i++)
        CPA16(Vb0 + (r8 + 32 * i) * 144 + c8 * 16, Vg + (size_t)(r8 + 32 * i) * 64 + c8 * 8);
    CP_COMMIT();
    CP_WAIT0();
    __syncthreads();

    // fragment lane-addresses (bytes)
    const uint32_t aQ = QPb + (16 * w + l7 + 8 * l8) * 144 + 16 * l16;  // +g*32 (A frags, Q & P)
    const uint32_t aK = (uint32_t)((l7 + 8 * l16) * 144 + 16 * l8);     // +Kbuf +ntp*2304 +g*32
    const uint32_t aV = (uint32_t)((l7 + 8 * l8) * 144 + 16 * l16);     // +Vbuf +g*2304 +ntp*32

    // Q fragments -> regs
    unsigned qf[4][4];
#pragma unroll
    for (int g = 0; g < 4; g++)
        LDSM4(qf[g][0], qf[g][1], qf[g][2], qf[g][3], aQ + g * 32);

    const int row0 = 16 * w + lr;
    const int row1 = row0 + 8;

    float m0 = -1e30f, m1 = -1e30f, l0 = 0.f, l1 = 0.f;
    float oacc[8][4];
#pragma unroll
    for (int i = 0; i < 8; i++)
#pragma unroll
        for (int q = 0; q < 4; q++) oacc[i][q] = 0.f;

    const int kt_last = 2 * qt + 1;

    for (int kt = 0; kt <= kt_last; kt++) {
        const int buf = kt & 1;
        const uint32_t Kbuf = Kb0 + buf * 9216;
        const uint32_t Vbuf = Vb0 + buf * 9216;

        if (kt < kt_last) {
            const __half* kg2 = Kg + (size_t)(kt + 1) * 64 * 64;
            const __half* vg2 = Vg + (size_t)(kt + 1) * 64 * 64;
            const uint32_t Kn = Kb0 + (buf ^ 1) * 9216;
            const uint32_t Vn = Vb0 + (buf ^ 1) * 9216;
#pragma unroll
            for (int i = 0; i < 2; i++)
                CPA16(Kn + (r8 + 32 * i) * 144 + c8 * 16, kg2 + (size_t)(r8 + 32 * i) * 64 + c8 * 8);
#pragma unroll
            for (int i = 0; i < 2; i++)
                CPA16(Vn + (r8 + 32 * i) * 144 + c8 * 16, vg2 + (size_t)(r8 + 32 * i) * 64 + c8 * 8);
            CP_COMMIT();
        }

        const int off = kt * 64 - qt * 128;
        const int lim = min(8, max(0, ((16 * w + 15 - off) >> 3) + 1));

        if (lim > 0) {
            // ---- S = Q K^T ----
            float s[8][4];
#pragma unroll
            for (int nt = 0; nt < 8; nt++) {
                s[nt][0] = 0.f; s[nt][1] = 0.f; s[nt][2] = 0.f; s[nt][3] = 0.f;
            }
            if (off < 0) {
#pragma unroll
                for (int g = 0; g < 4; g++) {
                    unsigned bb[8][2];
#pragma unroll
                    for (int ntp = 0; ntp < 4; ntp++)
                        LDSM4(bb[2 * ntp][0], bb[2 * ntp][1], bb[2 * ntp + 1][0], bb[2 * ntp + 1][1],
                              Kbuf + aK + ntp * 2304 + g * 32);
#pragma unroll
                    for (int nt = 0; nt < 8; nt++)
                        mma16(s[nt], qf[g], bb[nt]);
                }
            } else {
#pragma unroll
                for (int g = 0; g < 4; g++) {
                    unsigned bb[8][2];
#pragma unroll
                    for (int ntp = 0; ntp < 4; ntp++)
                        if (2 * ntp < lim)
                            LDSM4(bb[2 * ntp][0], bb[2 * ntp][1], bb[2 * ntp + 1][0], bb[2 * ntp + 1][1],
                                  Kbuf + aK + ntp * 2304 + g * 32);
#pragma unroll
                    for (int nt = 0; nt < 8; nt++)
                        if (nt < lim)
                            mma16(s[nt], qf[g], bb[nt]);
                }
                // causal mask
#pragma unroll
                for (int nt = 0; nt < 8; nt++) {
                    if (nt >= lim) {
                        s[nt][0] = s[nt][1] = s[nt][2] = s[nt][3] = -1e30f;
                    } else {
                        int c0 = off + nt * 8 + 2 * lc;
                        if (c0 > row0)     s[nt][0] = -1e30f;
                        if (c0 + 1 > row0) s[nt][1] = -1e30f;
                        if (c0 > row1)     s[nt][2] = -1e30f;
                        if (c0 + 1 > row1) s[nt][3] = -1e30f;
                    }
                }
            }

            // ---- register softmax (exp2 domain) ----
            float mx0 = -1e30f, mx1 = -1e30f;
#pragma unroll
            for (int nt = 0; nt < 8; nt++) {
                mx0 = fmaxf(mx0, fmaxf(s[nt][0], s[nt][1]));
                mx1 = fmaxf(mx1, fmaxf(s[nt][2], s[nt][3]));
            }
            mx0 = fmaxf(mx0, __shfl_xor_sync(0xffffffffu, mx0, 1));
            mx0 = fmaxf(mx0, __shfl_xor_sync(0xffffffffu, mx0, 2));
            mx1 = fmaxf(mx1, __shfl_xor_sync(0xffffffffu, mx1, 1));
            mx1 = fmaxf(mx1, __shfl_xor_sync(0xffffffffu, mx1, 2));
            float m0n = fmaxf(m0, mx0), m1n = fmaxf(m1, mx1);
            float a0 = ex2(m0 - m0n), a1 = ex2(m1 - m1n);
            m0 = m0n; m1 = m1n;

            float sum0 = 0.f, sum1 = 0.f;
#pragma unroll
            for (int nt = 0; nt < 8; nt++) {
                float e0 = ex2(s[nt][0] - m0n);
                float e1 = ex2(s[nt][1] - m0n);
                float e2 = ex2(s[nt][2] - m1n);
                float e3 = ex2(s[nt][3] - m1n);
                sum0 += e0 + e1;
                sum1 += e2 + e3;
                QP32[row0 * 36 + nt * 4 + lc] = f2h2(e0, e1);
                QP32[row1 * 36 + nt * 4 + lc] = f2h2(e2, e3);
            }
            sum0 += __shfl_xor_sync(0xffffffffu, sum0, 1);
            sum0 += __shfl_xor_sync(0xffffffffu, sum0, 2);
            sum1 += __shfl_xor_sync(0xffffffffu, sum1, 1);
            sum1 += __shfl_xor_sync(0xffffffffu, sum1, 2);
            l0 = l0 * a0 + sum0;
            l1 = l1 * a1 + sum1;

#pragma unroll
            for (int nt = 0; nt < 8; nt++) {
                oacc[nt][0] *= a0; oacc[nt][1] *= a0;
                oacc[nt][2] *= a1; oacc[nt][3] *= a1;
            }
            __syncwarp();

            // ---- O += P V ----
#pragma unroll
            for (int g = 0; g < 4; g++) {
                unsigned pa[4];
                LDSM4(pa[0], pa[1], pa[2], pa[3], aQ + g * 32);
                unsigned bb[8][2];
#pragma unroll
                for (int ntp = 0; ntp < 4; ntp++)
                    LDSM4T(bb[2 * ntp][0], bb[2 * ntp][1], bb[2 * ntp + 1][0], bb[2 * ntp + 1][1],
                           Vbuf + aV + g * 2304 + ntp * 32);
#pragma unroll
                for (int nt = 0; nt < 8; nt++)
                    mma16(oacc[nt], pa, bb[nt]);
            }
        }
        if (kt < kt_last) CP_WAIT0();
        __syncthreads();
    }

    // finalize -> half g_o
    float li0 = 1.f / l0, li1 = 1.f / l1;
    __half* Og = g_o + base + (size_t)qt * 128 * 64;
#pragma unroll
    for (int nt = 0; nt < 8; nt++) {
        int c = nt * 8 + 2 * lc;
        *(unsigned*)(Og + (size_t)row0 * 64 + c) = f2h2(oacc[nt][0] * li0, oacc[nt][1] * li0);
        *(unsigned*)(Og + (size_t)row1 * 64 + c) = f2h2(oacc[nt][2] * li1, oacc[nt][3] * li1);
    }
}

// ---------------------------------------------------------------------------
// Kernel 3: proj GEMM fp16. Block 128m x 128n, BK=32, warp 64x32, K=512.
// Both operands half via cp.async; ldmatrix frags; transpose epilogue.
// ---------------------------------------------------------------------------
__global__ void __launch_bounds__(256, 2) proj_gemm_kernel(
    const float* __restrict__ pb, float* __restrict__ out)
{
    extern __shared__ char smem[];
    const uint32_t sb = smem_u32(smem);
    const uint32_t Ab0 = sb;             // 2 x 128*80 = 20480
    const uint32_t Bb0 = sb + 20480;     // 2 x 128*80 = 20480

    const int b  = blockIdx.z;
    const int mT = blockIdx.x * 128;
    const int nT = blockIdx.y * 128;
    const int t = threadIdx.x, lane = t & 31, warp = t >> 5;
    const int wm = (warp & 1) * 64;
    const int wn = (warp >> 1) * 32;
    const int lr = lane >> 2, lc = lane & 3;
    const int l7 = lane & 7, l8 = (lane >> 3) & 1, l16 = lane >> 4;

    const __half* ob = g_o + (size_t)b * (NHEAD * NTOK * 64);

    float acc[4][4][4];
#pragma unroll
    for (int i = 0; i < 4; i++)
#pragma unroll
        for (int j = 0; j < 4; j++)
#pragma unroll
            for (int q = 0; q < 4; q++) acc[i][j][q] = 0.f;

    const int a_r = t >> 1, a_c = t & 1;
#define PROJ_ISSUE(kk, buf) do { \
    int head = (kk) >> 6, d0 = (kk) & 63; \
    const __half* src = ob + (size_t)head * (NTOK * 64); \
    uint32_t Ad = Ab0 + (buf) * 10240, Bd = Bb0 + (buf) * 10240; \
    _Pragma("unroll") \
    for (int i = 0; i < 2; i++) \
        CPA16(Ad + a_r * 80 + (a_c * 2 + i) * 16, \
              src + (size_t)(mT + a_r) * 64 + d0 + (a_c * 2 + i) * 8); \
    _Pragma("unroll") \
    for (int i = 0; i < 2; i++) \
        CPA16(Bd + a_r * 80 + (a_c * 2 + i) * 16, \
              g_pw + (size_t)(nT + a_r) * 512 + (kk) + (a_c * 2 + i) * 8); \
    CP_COMMIT(); } while (0)

    const uint32_t aAl = (uint32_t)((wm + l7 + 8 * l8) * 80 + 16 * l16);
    const uint32_t aBl = (uint32_t)((wn + l7 + 8 * l16) * 80 + 16 * l8);

    PROJ_ISSUE(0, 0);
    CP_WAIT0();
    __syncthreads();

    for (int it = 0; it < 16; it++) {
        const int buf = it & 1;
        if (it < 15) PROJ_ISSUE((it + 1) * 32, buf ^ 1);
        const uint32_t Ac = Ab0 + buf * 10240 + aAl;
        const uint32_t Bc = Bb0 + buf * 10240 + aBl;
#pragma unroll
        for (int kg = 0; kg < 2; kg++) {
            unsigned a[4][4], bb[4][2];
#pragma unroll
            for (int mi = 0; mi < 4; mi++)
                LDSM4(a[mi][0], a[mi][1], a[mi][2], a[mi][3],
                      Ac + mi * 1280 + kg * 32);
#pragma unroll
            for (int ntp = 0; ntp < 2; ntp++)
                LDSM4(bb[2 * ntp][0], bb[2 * ntp][1], bb[2 * ntp + 1][0], bb[2 * ntp + 1][1],
                      Bc + ntp * 1280 + kg * 32);
#pragma unroll
            for (int mi = 0; mi < 4; mi++)
#pragma unroll
                for (int ni = 0; ni < 4; ni++)
                    mma16(acc[mi][ni], a[mi], bb[ni]);
        }
        if (it < 15) CP_WAIT0();
        __syncthreads();
    }

    // transpose epilogue through smem: Cs[n][m] ld132 (float)
    float* Cs = (float*)smem;
#pragma unroll
    for (int ni = 0; ni < 4; ni++) {
        int n = wn + ni * 8 + 2 * lc;
#pragma unroll
        for (int mi = 0; mi < 4; mi++) {
            int m = wm + mi * 16 + lr;
            Cs[n * 132 + m]           = acc[mi][ni][0];
            Cs[(n + 1) * 132 + m]     = acc[mi][ni][1];
            Cs[n * 132 + m + 8]       = acc[mi][ni][2];
            Cs[(n + 1) * 132 + m + 8] = acc[mi][ni][3];
        }
    }
    __syncthreads();

#pragma unroll
    for (int i = 0; i < 16; i++) {
        int idx = t + i * 256;
        int n = idx >> 5, mq = (idx & 31) * 4;
        float bi = pb[nT + n];
        const float* src = &Cs[n * 132 + mq];
        float4 v;
        v.x = src[0] + bi; v.y = src[1] + bi; v.z = src[2] + bi; v.w = src[3] + bi;
        *(float4*)(out + (size_t)(b * 256 + nT + n) * NTOK + mT + mq) = v;
    }
}

// ---------------------------------------------------------------------------
extern "C" void kernel_launch(void* const* d_in, const int* in_sizes, int n_in,
                              void* d_out, int out_size)
{
    const float* x      = (const float*)d_in[0];
    const float* qkv_w  = (const float*)d_in[1];
    const float* qkv_b  = (const float*)d_in[2];
    const float* proj_w = (const float*)d_in[3];
    const float* proj_b = (const float*)d_in[4];
    float* out = (float*)d_out;

    const int qkv_smem  = 37888;
    const int attn_smem = 55296;
    const int proj_smem = 128 * 132 * 4;   // 67584 (epilogue dominates)
    cudaFuncSetAttribute(qkv_gemm_kernel, cudaFuncAttributeMaxDynamicSharedMemorySize, qkv_smem);
    cudaFuncSetAttribute(attn_kernel, cudaFuncAttributeMaxDynamicSharedMemorySize, attn_smem);
    cudaFuncSetAttribute(proj_gemm_kernel, cudaFuncAttributeMaxDynamicSharedMemorySize, proj_smem);

    cvt_kernel<<<(X_F4 + W_F4 + PW_F4) / 256, 256>>>(x, qkv_w, proj_w);
    qkv_gemm_kernel<<<dim3(8, 12, BATCH), 256, qkv_smem>>>(qkv_b);
    attn_kernel<<<dim3(8, NHEAD, BATCH), 256, attn_smem>>>();
    proj_gemm_kernel<<<dim3(8, 2, BATCH), 256, proj_smem>>>(proj_b, out);
}

// round 9
// speedup vs baseline: 6.6553x; 1.0104x over previous
#include <cuda_runtime.h>
#include <cuda_fp16.h>
#include <cstdint>

#define BATCH   16
#define IN_CH   256
#define NTOK    1024
#define NHEAD   8
// SCALE * log2(e): softmax done in exp2 domain
#define QSCALE  0.18033688f

// Scratch
__device__ __align__(16) __half g_x[BATCH * IN_CH * NTOK];     // x in half
__device__ __align__(16) __half g_w[1536 * IN_CH];             // qkv_w half
__device__ __align__(16) __half g_pw[256 * 512];               // proj_w half
__device__ __align__(16) __half g_q[BATCH * NHEAD * NTOK * 64];
__device__ __align__(16) __half g_k[BATCH * NHEAD * NTOK * 64];
__device__ __align__(16) __half g_v[BATCH * NHEAD * NTOK * 64];
__device__ __align__(16) __half g_o[BATCH * NHEAD * NTOK * 64];

__device__ __forceinline__ unsigned f2h2(float lo, float hi) {
    unsigned r;
    asm("cvt.rn.f16x2.f32 %0, %1, %2;" : "=r"(r) : "f"(hi), "f"(lo));
    return r;
}
__device__ __forceinline__ float ex2(float x) {
    float r;
    asm("ex2.approx.f32 %0, %1;" : "=f"(r) : "f"(x));
    return r;
}
__device__ __forceinline__ uint32_t smem_u32(const void* p) {
    uint32_t a;
    asm("{ .reg .u64 t; cvta.to.shared.u64 t, %1; cvt.u32.u64 %0, t; }" : "=r"(a) : "l"(p));
    return a;
}
__device__ __forceinline__ void mma16(float* d, const unsigned* a, const unsigned* b) {
    asm volatile(
        "mma.sync.aligned.m16n8k16.row.col.f32.f16.f16.f32 "
        "{%0,%1,%2,%3}, {%4,%5,%6,%7}, {%8,%9}, {%0,%1,%2,%3};\n"
        : "+f"(d[0]), "+f"(d[1]), "+f"(d[2]), "+f"(d[3])
        : "r"(a[0]), "r"(a[1]), "r"(a[2]), "r"(a[3]), "r"(b[0]), "r"(b[1]));
}
#define LDSM4(r0, r1, r2, r3, addr) \
    asm volatile("ldmatrix.sync.aligned.m8n8.x4.shared.b16 {%0,%1,%2,%3}, [%4];" \
        : "=r"(r0), "=r"(r1), "=r"(r2), "=r"(r3) : "r"(addr))
#define LDSM4T(r0, r1, r2, r3, addr) \
    asm volatile("ldmatrix.sync.aligned.m8n8.x4.trans.shared.b16 {%0,%1,%2,%3}, [%4];" \
        : "=r"(r0), "=r"(r1), "=r"(r2), "=r"(r3) : "r"(addr))
#define CPA16(dst, src) \
    asm volatile("cp.async.cg.shared.global [%0], [%1], 16;" :: "r"(dst), "l"(src))
#define CP_COMMIT() asm volatile("cp.async.commit_group;" ::: "memory")
#define CP_WAIT1()  asm volatile("cp.async.wait_group 1;" ::: "memory")

// ---------------------------------------------------------------------------
// Kernel 0: fp32 -> fp16 pre-convert (x, qkv_w, proj_w). One float4/thread.
// ---------------------------------------------------------------------------
#define X_F4   1048576            // 16*256*1024 / 4
#define W_F4   98304              // 1536*256 / 4
#define PW_F4  32768              // 256*512 / 4
__global__ void cvt_kernel(const float* __restrict__ x,
                           const float* __restrict__ w,
                           const float* __restrict__ pw)
{
    int i = blockIdx.x * 256 + threadIdx.x;
    const float4* src;
    __half* dst;
    int j;
    if (i < X_F4)            { src = (const float4*)x;  dst = g_x;  j = i; }
    else if (i < X_F4 + W_F4){ src = (const float4*)w;  dst = g_w;  j = i - X_F4; }
    else                     { src = (const float4*)pw; dst = g_pw; j = i - X_F4 - W_F4; }
    float4 v = src[j];
    *(uint2*)(dst + 4 * (size_t)j) = make_uint2(f2h2(v.x, v.y), f2h2(v.z, v.w));
}

// ---------------------------------------------------------------------------
// Kernel 1: QKV GEMM fp16. Block 128m x 128n, BK=32, 8 warps (2m x 4n),
// warp 64x32. A tile [k32][m128] pitch 272B (ldmatrix.trans), B [n128][k32]
// pitch 80B. 3-stage cp.async pipeline.
// ---------------------------------------------------------------------------
__global__ void __launch_bounds__(256, 2) qkv_gemm_kernel(
    const float* __restrict__ bias)
{
    extern __shared__ char smem[];
    const uint32_t sb = smem_u32(smem);
    const uint32_t Ab0 = sb;             // 3 x 32*272  = 26112
    const uint32_t Bb0 = sb + 26112;     // 3 x 128*80  = 30720

    const int b  = blockIdx.z;
    const int mT = blockIdx.x * 128;
    const int nT = blockIdx.y * 128;
    const int t = threadIdx.x, lane = t & 31, warp = t >> 5;
    const int wm = (warp & 1) * 64;
    const int wn = (warp >> 1) * 32;
    const int lr = lane >> 2, lc = lane & 3;
    const int l7 = lane & 7, l8 = (lane >> 3) & 1, l16 = lane >> 4;

    const __half* xb = g_x + (size_t)b * (IN_CH * NTOK);

    float acc[4][4][4];
#pragma unroll
    for (int i = 0; i < 4; i++)
#pragma unroll
        for (int j = 0; j < 4; j++)
#pragma unroll
            for (int q = 0; q < 4; q++) acc[i][j][q] = 0.f;

    const int a_k = t >> 3, a_c = t & 7;
    const int b_n = t >> 1, b_c = t & 1;
#define QKV_ISSUE(kk, buf) do { \
    uint32_t Ad = Ab0 + (buf) * 8704, Bd = Bb0 + (buf) * 10240; \
    _Pragma("unroll") \
    for (int i = 0; i < 2; i++) \
        CPA16(Ad + a_k * 272 + (a_c * 2 + i) * 16, \
              xb + (size_t)((kk) + a_k) * NTOK + mT + (a_c * 2 + i) * 8); \
    _Pragma("unroll") \
    for (int i = 0; i < 2; i++) \
        CPA16(Bd + b_n * 80 + (b_c * 2 + i) * 16, \
              g_w + (size_t)(nT + b_n) * IN_CH + (kk) + (b_c * 2 + i) * 8); \
    CP_COMMIT(); } while (0)

    const uint32_t aAl = (uint32_t)((l7 + 8 * l16) * 272 + 16 * l8 + wm * 2);
    const uint32_t aBl = (uint32_t)((wn + l7 + 8 * l16) * 80 + 16 * l8);

    QKV_ISSUE(0, 0);
    QKV_ISSUE(32, 1);

#pragma unroll
    for (int it = 0; it < 8; it++) {
        const int buf = it % 3;
        CP_WAIT1();
        __syncthreads();
        if (it < 6) QKV_ISSUE((it + 2) * 32, (it + 2) % 3); else CP_COMMIT();
        const uint32_t Ac = Ab0 + buf * 8704 + aAl;
        const uint32_t Bc = Bb0 + buf * 10240 + aBl;
#pragma unroll
        for (int kg = 0; kg < 2; kg++) {
            unsigned a[4][4], bb[4][2];
#pragma unroll
            for (int mi = 0; mi < 4; mi++)
                LDSM4T(a[mi][0], a[mi][1], a[mi][2], a[mi][3],
                       Ac + kg * 4352 + mi * 32);
#pragma unroll
            for (int ntp = 0; ntp < 2; ntp++)
                LDSM4(bb[2 * ntp][0], bb[2 * ntp][1], bb[2 * ntp + 1][0], bb[2 * ntp + 1][1],
                      Bc + ntp * 1280 + kg * 32);
#pragma unroll
            for (int mi = 0; mi < 4; mi++)
#pragma unroll
                for (int ni = 0; ni < 4; ni++)
                    mma16(acc[mi][ni], a[mi], bb[ni]);
        }
    }

    // epilogue -> half g_q/g_k/g_v [b,h,tok,d]; q pre-scaled by SCALE*log2e
#pragma unroll
    for (int ni = 0; ni < 4; ni++) {
        int o = nT + wn + ni * 8 + 2 * lc;
        __half* dst;
        float sc = 1.f;
        if (o < 512)       { dst = g_q; sc = QSCALE; }
        else if (o < 1024) { dst = g_k; }
        else               { dst = g_v; }
        int head = (o >> 6) & 7, d = o & 63;
        float b0 = bias[o], b1 = bias[o + 1];
        __half* base = dst + ((size_t)(b * NHEAD + head) * NTOK) * 64 + d;
#pragma unroll
        for (int mi = 0; mi < 4; mi++) {
            int r = mT + wm + mi * 16 + lr;
            *(unsigned*)(base + (size_t)r * 64) =
                f2h2((acc[mi][ni][0] + b0) * sc, (acc[mi][ni][1] + b1) * sc);
            *(unsigned*)(base + (size_t)(r + 8) * 64) =
                f2h2((acc[mi][ni][2] + b0) * sc, (acc[mi][ni][3] + b1) * sc);
        }
    }
}

// ---------------------------------------------------------------------------
// Kernel 2: causal flash attention fp16, FA2 register softmax + ldmatrix.
// BM=128 (8 warps x 16 rows), BN=64. 3-stage cp.async K/V pipeline.
// ---------------------------------------------------------------------------
__global__ void __launch_bounds__(256, 2) attn_kernel()
{
    extern __shared__ char smem[];
    const uint32_t sb = smem_u32(smem);
    const uint32_t QPb = sb;             // [128][72h] = 18432
    const uint32_t Kb0 = sb + 18432;     // 3 x [64][72h] = 27648
    const uint32_t Vb0 = sb + 46080;     // 3 x [64][72h] = 27648
    unsigned* QP32 = (unsigned*)smem;

    const int t = threadIdx.x, lane = t & 31, w = t >> 5;
    const int lr = lane >> 2, lc = lane & 3;
    const int l7 = lane & 7, l8 = (lane >> 3) & 1, l16 = lane >> 4;
    const int qt = 7 - blockIdx.x;       // heavy blocks first
    const int h = blockIdx.y, b = blockIdx.z;

    const size_t base = (size_t)(b * NHEAD + h) * (NTOK * 64);
    const __half* Qg = g_q + base + (size_t)qt * 128 * 64;
    const __half* Kg = g_k + base;
    const __half* Vg = g_v + base;

    const int r8 = t >> 3, c8 = t & 7;

#define KV_ISSUE(kt2, buf) do { \
    const __half* kg2 = Kg + (size_t)(kt2) * 64 * 64; \
    const __half* vg2 = Vg + (size_t)(kt2) * 64 * 64; \
    uint32_t Kn = Kb0 + (buf) * 9216, Vn = Vb0 + (buf) * 9216; \
    _Pragma("unroll") \
    for (int i = 0; i < 2; i++) \
        CPA16(Kn + (r8 + 32 * i) * 144 + c8 * 16, kg2 + (size_t)(r8 + 32 * i) * 64 + c8 * 8); \
    _Pragma("unroll") \
    for (int i = 0; i < 2; i++) \
        CPA16(Vn + (r8 + 32 * i) * 144 + c8 * 16, vg2 + (size_t)(r8 + 32 * i) * 64 + c8 * 8); \
    CP_COMMIT(); } while (0)

    const int kt_last = 2 * qt + 1;

    // prologue: group0 = Q + K0 + V0; group1 = K1 + V1
#pragma unroll
    for (int i = 0; i < 4; i++)
        CPA16(QPb + (r8 + 32 * i) * 144 + c8 * 16, Qg + (size_t)(r8 + 32 * i) * 64 + c8 * 8);
    KV_ISSUE(0, 0);
    KV_ISSUE(1, 1);
    CP_WAIT1();
    __syncthreads();

    // fragment lane-addresses (bytes)
    const uint32_t aQ = QPb + (16 * w + l7 + 8 * l8) * 144 + 16 * l16;
    const uint32_t aK = (uint32_t)((l7 + 8 * l16) * 144 + 16 * l8);
    const uint32_t aV = (uint32_t)((l7 + 8 * l8) * 144 + 16 * l16);

    // Q fragments -> regs
    unsigned qf[4][4];
#pragma unroll
    for (int g = 0; g < 4; g++)
        LDSM4(qf[g][0], qf[g][1], qf[g][2], qf[g][3], aQ + g * 32);

    const int row0 = 16 * w + lr;
    const int row1 = row0 + 8;

    float m0 = -1e30f, m1 = -1e30f, l0 = 0.f, l1 = 0.f;
    float oacc[8][4];
#pragma unroll
    for (int i = 0; i < 8; i++)
#pragma unroll
        for (int q = 0; q < 4; q++) oacc[i][q] = 0.f;

    for (int kt = 0; kt <= kt_last; kt++) {
        const int buf = kt % 3;
        const uint32_t Kbuf = Kb0 + buf * 9216;
        const uint32_t Vbuf = Vb0 + buf * 9216;

        if (kt > 0) { CP_WAIT1(); __syncthreads(); }
        if (kt + 2 <= kt_last) KV_ISSUE(kt + 2, (kt + 2) % 3); else CP_COMMIT();

        const int off = kt * 64 - qt * 128;
        const int lim = min(8, max(0, ((16 * w + 15 - off) >> 3) + 1));

        if (lim > 0) {
            // ---- S = Q K^T ----
            float s[8][4];
#pragma unroll
            for (int nt = 0; nt < 8; nt++) {
                s[nt][0] = 0.f; s[nt][1] = 0.f; s[nt][2] = 0.f; s[nt][3] = 0.f;
            }
            if (off < 0) {
#pragma unroll
                for (int g = 0; g < 4; g++) {
                    unsigned bb[8][2];
#pragma unroll
                    for (int ntp = 0; ntp < 4; ntp++)
                        LDSM4(bb[2 * ntp][0], bb[2 * ntp][1], bb[2 * ntp + 1][0], bb[2 * ntp + 1][1],
                              Kbuf + aK + ntp * 2304 + g * 32);
#pragma unroll
                    for (int nt = 0; nt < 8; nt++)
                        mma16(s[nt], qf[g], bb[nt]);
                }
            } else {
#pragma unroll
                for (int g = 0; g < 4; g++) {
                    unsigned bb[8][2];
#pragma unroll
                    for (int ntp = 0; ntp < 4; ntp++)
                        if (2 * ntp < lim)
                            LDSM4(bb[2 * ntp][0], bb[2 * ntp][1], bb[2 * ntp + 1][0], bb[2 * ntp + 1][1],
                                  Kbuf + aK + ntp * 2304 + g * 32);
#pragma unroll
                    for (int nt = 0; nt < 8; nt++)
                        if (nt < lim)
                            mma16(s[nt], qf[g], bb[nt]);
                }
#pragma unroll
                for (int nt = 0; nt < 8; nt++) {
                    if (nt >= lim) {
                        s[nt][0] = s[nt][1] = s[nt][2] = s[nt][3] = -1e30f;
                    } else {
                        int c0 = off + nt * 8 + 2 * lc;
                        if (c0 > row0)     s[nt][0] = -1e30f;
                        if (c0 + 1 > row0) s[nt][1] = -1e30f;
                        if (c0 > row1)     s[nt][2] = -1e30f;
                        if (c0 + 1 > row1) s[nt][3] = -1e30f;
                    }
                }
            }

            // ---- register softmax (exp2 domain) ----
            float mx0 = -1e30f, mx1 = -1e30f;
#pragma unroll
            for (int nt = 0; nt < 8; nt++) {
                mx0 = fmaxf(mx0, fmaxf(s[nt][0], s[nt][1]));
                mx1 = fmaxf(mx1, fmaxf(s[nt][2], s[nt][3]));
            }
            mx0 = fmaxf(mx0, __shfl_xor_sync(0xffffffffu, mx0, 1));
            mx0 = fmaxf(mx0, __shfl_xor_sync(0xffffffffu, mx0, 2));
            mx1 = fmaxf(mx1, __shfl_xor_sync(0xffffffffu, mx1, 1));
            mx1 = fmaxf(mx1, __shfl_xor_sync(0xffffffffu, mx1, 2));
            float m0n = fmaxf(m0, mx0), m1n = fmaxf(m1, mx1);
            float a0 = ex2(m0 - m0n), a1 = ex2(m1 - m1n);
            m0 = m0n; m1 = m1n;

            float sum0 = 0.f, sum1 = 0.f;
#pragma unroll
            for (int nt = 0; nt < 8; nt++) {
                float e0 = ex2(s[nt][0] - m0n);
                float e1 = ex2(s[nt][1] - m0n);
                float e2 = ex2(s[nt][2] - m1n);
                float e3 = ex2(s[nt][3] - m1n);
                sum0 += e0 + e1;
                sum1 += e2 + e3;
                QP32[row0 * 36 + nt * 4 + lc] = f2h2(e0, e1);
                QP32[row1 * 36 + nt * 4 + lc] = f2h2(e2, e3);
            }
            sum0 += __shfl_xor_sync(0xffffffffu, sum0, 1);
            sum0 += __shfl_xor_sync(0xffffffffu, sum0, 2);
            sum1 += __shfl_xor_sync(0xffffffffu, sum1, 1);
            sum1 += __shfl_xor_sync(0xffffffffu, sum1, 2);
            l0 = l0 * a0 + sum0;
            l1 = l1 * a1 + sum1;

#pragma unroll
            for (int nt = 0; nt < 8; nt++) {
                oacc[nt][0] *= a0; oacc[nt][1] *= a0;
                oacc[nt][2] *= a1; oacc[nt][3] *= a1;
            }
            __syncwarp();

            // ---- O += P V ----
#pragma unroll
            for (int g = 0; g < 4; g++) {
                unsigned pa[4];
                LDSM4(pa[0], pa[1], pa[2], pa[3], aQ + g * 32);
                unsigned bb[8][2];
#pragma unroll
                for (int ntp = 0; ntp < 4; ntp++)
                    LDSM4T(bb[2 * ntp][0], bb[2 * ntp][1], bb[2 * ntp + 1][0], bb[2 * ntp + 1][1],
                           Vbuf + aV + g * 2304 + ntp * 32);
#pragma unroll
                for (int nt = 0; nt < 8; nt++)
                    mma16(oacc[nt], pa, bb[nt]);
            }
        }
    }

    // finalize -> half g_o
    float li0 = 1.f / l0, li1 = 1.f / l1;
    __half* Og = g_o + base + (size_t)qt * 128 * 64;
#pragma unroll
    for (int nt = 0; nt < 8; nt++) {
        int c = nt * 8 + 2 * lc;
        *(unsigned*)(Og + (size_t)row0 * 64 + c) = f2h2(oacc[nt][0] * li0, oacc[nt][1] * li0);
        *(unsigned*)(Og + (size_t)row1 * 64 + c) = f2h2(oacc[nt][2] * li1, oacc[nt][3] * li1);
    }
}

// ---------------------------------------------------------------------------
// Kernel 3: proj GEMM fp16. Block 128m x 128n, BK=32, warp 64x32, K=512.
// 3-stage cp.async pipeline; ldmatrix frags; transpose epilogue.
// ---------------------------------------------------------------------------
__global__ void __launch_bounds__(256, 2) proj_gemm_kernel(
    const float* __restrict__ pb, float* __restrict__ out)
{
    extern __shared__ char smem[];
    const uint32_t sb = smem_u32(smem);
    const uint32_t Ab0 = sb;             // 3 x 128*80 = 30720
    const uint32_t Bb0 = sb + 30720;     // 3 x 128*80 = 30720

    const int b  = blockIdx.z;
    const int mT = blockIdx.x * 128;
    const int nT = blockIdx.y * 128;
    const int t = threadIdx.x, lane = t & 31, warp = t >> 5;
    const int wm = (warp & 1) * 64;
    const int wn = (warp >> 1) * 32;
    const int lr = lane >> 2, lc = lane & 3;
    const int l7 = lane & 7, l8 = (lane >> 3) & 1, l16 = lane >> 4;

    const __half* ob = g_o + (size_t)b * (NHEAD * NTOK * 64);

    float acc[4][4][4];
#pragma unroll
    for (int i = 0; i < 4; i++)
#pragma unroll
        for (int j = 0; j < 4; j++)
#pragma unroll
            for (int q = 0; q < 4; q++) acc[i][j][q] = 0.f;

    const int a_r = t >> 1, a_c = t & 1;
#define PROJ_ISSUE(kk, buf) do { \
    int head = (kk) >> 6, d0 = (kk) & 63; \
    const __half* src = ob + (size_t)head * (NTOK * 64); \
    uint32_t Ad = Ab0 + (buf) * 10240, Bd = Bb0 + (buf) * 10240; \
    _Pragma("unroll") \
    for (int i = 0; i < 2; i++) \
        CPA16(Ad + a_r * 80 + (a_c * 2 + i) * 16, \
              src + (size_t)(mT + a_r) * 64 + d0 + (a_c * 2 + i) * 8); \
    _Pragma("unroll") \
    for (int i = 0; i < 2; i++) \
        CPA16(Bd + a_r * 80 + (a_c * 2 + i) * 16, \
              g_pw + (size_t)(nT + a_r) * 512 + (kk) + (a_c * 2 + i) * 8); \
    CP_COMMIT(); } while (0)

    const uint32_t aAl = (uint32_t)((wm + l7 + 8 * l8) * 80 + 16 * l16);
    const uint32_t aBl = (uint32_t)((wn + l7 + 8 * l16) * 80 + 16 * l8);

    PROJ_ISSUE(0, 0);
    PROJ_ISSUE(32, 1);

#pragma unroll
    for (int it = 0; it < 16; it++) {
        const int buf = it % 3;
        CP_WAIT1();
        __syncthreads();
        if (it < 14) PROJ_ISSUE((it + 2) * 32, (it + 2) % 3); else CP_COMMIT();
        const uint32_t Ac = Ab0 + buf * 10240 + aAl;
        const uint32_t Bc = Bb0 + buf * 10240 + aBl;
#pragma unroll
        for (int kg = 0; kg < 2; kg++) {
            unsigned a[4][4], bb[4][2];
#pragma unroll
            for (int mi = 0; mi < 4; mi++)
                LDSM4(a[mi][0], a[mi][1], a[mi][2], a[mi][3],
                      Ac + mi * 1280 + kg * 32);
#pragma unroll
            for (int ntp = 0; ntp < 2; ntp++)
                LDSM4(bb[2 * ntp][0], bb[2 * ntp][1], bb[2 * ntp + 1][0], bb[2 * ntp + 1][1],
                      Bc + ntp * 1280 + kg * 32);
#pragma unroll
            for (int mi = 0; mi < 4; mi++)
#pragma unroll
                for (int ni = 0; ni < 4; ni++)
                    mma16(acc[mi][ni], a[mi], bb[ni]);
        }
    }
    __syncthreads();

    // transpose epilogue through smem: Cs[n][m] ld132 (float)
    float* Cs = (float*)smem;
#pragma unroll
    for (int ni = 0; ni < 4; ni++) {
        int n = wn + ni * 8 + 2 * lc;
#pragma unroll
        for (int mi = 0; mi < 4; mi++) {
            int m = wm + mi * 16 + lr;
            Cs[n * 132 + m]           = acc[mi][ni][0];
            Cs[(n + 1) * 132 + m]     = acc[mi][ni][1];
            Cs[n * 132 + m + 8]       = acc[mi][ni][2];
            Cs[(n + 1) * 132 + m + 8] = acc[mi][ni][3];
        }
    }
    __syncthreads();

#pragma unroll
    for (int i = 0; i < 16; i++) {
        int idx = t + i * 256;
        int n = idx >> 5, mq = (idx & 31) * 4;
        float bi = pb[nT + n];
        const float* src = &Cs[n * 132 + mq];
        float4 v;
        v.x = src[0] + bi; v.y = src[1] + bi; v.z = src[2] + bi; v.w = src[3] + bi;
        *(float4*)(out + (size_t)(b * 256 + nT + n) * NTOK + mT + mq) = v;
    }
}

// ---------------------------------------------------------------------------
extern "C" void kernel_launch(void* const* d_in, const int* in_sizes, int n_in,
                              void* d_out, int out_size)
{
    const float* x      = (const float*)d_in[0];
    const float* qkv_w  = (const float*)d_in[1];
    const float* qkv_b  = (const float*)d_in[2];
    const float* proj_w = (const float*)d_in[3];
    const float* proj_b = (const float*)d_in[4];
    float* out = (float*)d_out;

    const int qkv_smem  = 56832;
    const int attn_smem = 73728;
    const int proj_smem = 128 * 132 * 4;   // 67584 (epilogue dominates)
    cudaFuncSetAttribute(qkv_gemm_kernel, cudaFuncAttributeMaxDynamicSharedMemorySize, qkv_smem);
    cudaFuncSetAttribute(attn_kernel, cudaFuncAttributeMaxDynamicSharedMemorySize, attn_smem);
    cudaFuncSetAttribute(proj_gemm_kernel, cudaFuncAttributeMaxDynamicSharedMemorySize, proj_smem);

    cvt_kernel<<<(X_F4 + W_F4 + PW_F4) / 256, 256>>>(x, qkv_w, proj_w);
    qkv_gemm_kernel<<<dim3(8, 12, BATCH), 256, qkv_smem>>>(qkv_b);
    attn_kernel<<<dim3(8, NHEAD, BATCH), 256, attn_smem>>>();
    proj_gemm_kernel<<<dim3(8, 2, BATCH), 256, proj_smem>>>(proj_b, out);
}